// round 6
// baseline (speedup 1.0000x reference)
#include <cuda_runtime.h>
#include <cuda_bf16.h>
#include <cstdint>

#define NN 50000
#define DIN1 64
#define DH 128

// ---------------- scratch (device globals; no allocation allowed) ----------------
__device__ float4 g_agg1[NN * (DIN1 / 4)];        // [NN, 64]
__device__ float4 g_h   [NN * (DH   / 4)];        // [NN, 128]
__device__ float4 g_agg2[NN * (DH   / 4)];        // [NN, 128]
__device__ float  g_inv [NN];
__device__ int    g_cnt [NN];
__device__ float4 g_W1t [(2 * DIN1 * DH) / 4];    // k-major combined [128, 128]
__device__ float4 g_W2t [(2 * DH   * DH) / 4];    // k-major combined [256, 128]

// ---------------- helpers ----------------
__device__ __forceinline__ unsigned long long f2ull(float lo, float hi) {
    unsigned long long r;
    asm("mov.b64 %0, {%1, %2};" : "=l"(r) : "f"(lo), "f"(hi));
    return r;
}
__device__ __forceinline__ float2 ull2f(unsigned long long v) {
    float2 r;
    asm("mov.b64 {%0, %1}, %2;" : "=f"(r.x), "=f"(r.y) : "l"(v));
    return r;
}
// packed fp32x2 FMA (Blackwell; 2x FFMA rate, only reachable via PTX)
__device__ __forceinline__ unsigned long long fma2(unsigned long long a,
                                                   unsigned long long b,
                                                   unsigned long long c) {
    unsigned long long d;
    asm("fma.rn.f32x2 %0, %1, %2, %3;" : "=l"(d) : "l"(a), "l"(b), "l"(c));
    return d;
}
// vector reduction (no return) — 1 instr moves 16B into L2 atomic ALU
__device__ __forceinline__ void red_add4(float* p, float4 v) {
    asm volatile("red.global.add.v4.f32 [%0], {%1, %2, %3, %4};"
                 :: "l"(p), "f"(v.x), "f"(v.y), "f"(v.z), "f"(v.w) : "memory");
}

// ---------------- tiny prep kernels ----------------
__global__ void zero_kernel(float4* __restrict__ p, int n4) {
    int i = blockIdx.x * blockDim.x + threadIdx.x;
    if (i < n4) p[i] = make_float4(0.f, 0.f, 0.f, 0.f);
}

__global__ void count_kernel(const int* __restrict__ dst, int* __restrict__ cnt, int E) {
    int e = blockIdx.x * blockDim.x + threadIdx.x;
    if (e < E) atomicAdd(&cnt[__ldg(dst + e)], 1);
}

__global__ void inv_kernel(const int* __restrict__ cnt, float* __restrict__ inv, int n) {
    int i = blockIdx.x * blockDim.x + threadIdx.x;
    if (i < n) {
        int c = cnt[i];
        inv[i] = 1.0f / (float)(c > 0 ? c : 1);
    }
}

// Build k-major combined weights: Wt[k][c] = Wl[c][k] (k<DIN) else Wr[c][k-DIN]
__global__ void prep_w(const float* __restrict__ Wl1, const float* __restrict__ Wr1,
                       const float* __restrict__ Wl2, const float* __restrict__ Wr2) {
    int i = blockIdx.x * blockDim.x + threadIdx.x;
    float* w1 = (float*)g_W1t;
    float* w2 = (float*)g_W2t;
    const int n1 = 2 * DIN1 * DH;   // 16384
    const int n2 = 2 * DH * DH;     // 32768
    if (i < n1) {
        int k = i >> 7, c = i & 127;
        w1[i] = (k < DIN1) ? Wl1[c * DIN1 + k] : Wr1[c * DIN1 + (k - DIN1)];
    } else if (i < n1 + n2) {
        int j = i - n1;
        int k = j >> 7, c = j & 127;
        w2[j] = (k < DH) ? Wl2[c * DH + k] : Wr2[c * DH + (k - DH)];
    }
}

// ---------------- scatter: agg[dst] += x[src], vector red, C4 float4s per row ----
template <int C4>
__global__ void scatter_kernel(const int* __restrict__ src, const int* __restrict__ dst,
                               const float* __restrict__ xin, float* __restrict__ agg, int E) {
    int idx = blockIdx.x * blockDim.x + threadIdx.x;
    int e = idx >> (C4 == 16 ? 4 : 5);
    if (e >= E) return;
    int c = idx & (C4 - 1);
    int s = __ldg(src + e);
    int d = __ldg(dst + e);
    float4 v = __ldg((const float4*)xin + (size_t)s * C4 + c);
    red_add4((float*)((float4*)agg + (size_t)d * C4 + c), v);
}

// ---------------- fused GEMM: out = relu([agg*inv | x] @ Wt + b) ------------------
// K = 2*DIN concat dim. BM=128 rows/block, BN=128 (full), BK=16, 256 thr, 8x8 microtile,
// packed f32x2 accumulation (row-pairs), full W resident in SMEM (k-major).
template <int K>
__launch_bounds__(256, 1)
__global__ void gemm_kernel(const float* __restrict__ agg, const float* __restrict__ xin,
                            const float* __restrict__ Wt, const float* __restrict__ bias,
                            const float* __restrict__ inv, float* __restrict__ out, int nrows) {
    constexpr int DIN = K / 2;
    extern __shared__ float smem[];
    float* sW = smem;               // K * 128
    float* sA = smem + K * 128;     // 16 * 128 (k-major: sA[k][row])
    const int tid = threadIdx.x;

    // stage full weight block (contiguous, coalesced)
    for (int i = tid; i < K * 32; i += 256)
        ((float4*)sW)[i] = ((const float4*)Wt)[i];

    const int rowBase = blockIdx.x * 128;
    const int tc = tid & 15;        // col group: cols tc*8..tc*8+7
    const int tr = tid >> 4;        // row group: rows tr*8..tr*8+7

    unsigned long long acc[4][8];   // [row-pair][col]
#pragma unroll
    for (int rp = 0; rp < 4; rp++)
#pragma unroll
        for (int c = 0; c < 8; c++) acc[rp][c] = 0ull;

    for (int kb = 0; kb < K; kb += 16) {
        // stage A chunk transposed: sA[k][row], k in [kb, kb+16)
#pragma unroll
        for (int j = 0; j < 2; j++) {
            int item = tid + 256 * j;          // 0..511
            int row  = item >> 2;              // 0..127
            int kq   = item & 3;               // which float4 of the 16 k's
            int kg   = kb + kq * 4;
            int rg   = rowBase + row;
            float4 v = make_float4(0.f, 0.f, 0.f, 0.f);
            if (rg < nrows) {
                if (kg < DIN) {
                    v = __ldg((const float4*)(agg + (size_t)rg * DIN + kg));
                    float s = __ldg(inv + rg);
                    v.x *= s; v.y *= s; v.z *= s; v.w *= s;
                } else {
                    v = __ldg((const float4*)(xin + (size_t)rg * DIN + (kg - DIN)));
                }
            }
            float* d = &sA[(kq * 4) * 128 + row];
            d[0] = v.x; d[128] = v.y; d[256] = v.z; d[384] = v.w;
        }
        __syncthreads();

#pragma unroll
        for (int k = 0; k < 16; k++) {
            const float4 a0 = *(const float4*)&sA[k * 128 + tr * 8];
            const float4 a1 = *(const float4*)&sA[k * 128 + tr * 8 + 4];
            const float4 w0 = *(const float4*)&sW[(kb + k) * 128 + tc * 8];
            const float4 w1 = *(const float4*)&sW[(kb + k) * 128 + tc * 8 + 4];
            unsigned long long a2[4];
            a2[0] = f2ull(a0.x, a0.y);
            a2[1] = f2ull(a0.z, a0.w);
            a2[2] = f2ull(a1.x, a1.y);
            a2[3] = f2ull(a1.z, a1.w);
            float wv[8] = {w0.x, w0.y, w0.z, w0.w, w1.x, w1.y, w1.z, w1.w};
#pragma unroll
            for (int c = 0; c < 8; c++) {
                unsigned long long w2 = f2ull(wv[c], wv[c]);
#pragma unroll
                for (int rp = 0; rp < 4; rp++)
                    acc[rp][c] = fma2(a2[rp], w2, acc[rp][c]);
            }
        }
        __syncthreads();
    }

    // epilogue: bias + relu + store
    float bb[8];
#pragma unroll
    for (int c = 0; c < 8; c++) bb[c] = __ldg(bias + tc * 8 + c);

#pragma unroll
    for (int rp = 0; rp < 4; rp++) {
        float v0[8], v1[8];
#pragma unroll
        for (int c = 0; c < 8; c++) {
            float2 p = ull2f(acc[rp][c]);
            v0[c] = p.x; v1[c] = p.y;
        }
        int r0 = rowBase + tr * 8 + rp * 2;
        int r1 = r0 + 1;
        if (r0 < nrows) {
            float* o = out + (size_t)r0 * 128 + tc * 8;
            float4 q0, q1;
            q0.x = fmaxf(v0[0] + bb[0], 0.f); q0.y = fmaxf(v0[1] + bb[1], 0.f);
            q0.z = fmaxf(v0[2] + bb[2], 0.f); q0.w = fmaxf(v0[3] + bb[3], 0.f);
            q1.x = fmaxf(v0[4] + bb[4], 0.f); q1.y = fmaxf(v0[5] + bb[5], 0.f);
            q1.z = fmaxf(v0[6] + bb[6], 0.f); q1.w = fmaxf(v0[7] + bb[7], 0.f);
            ((float4*)o)[0] = q0; ((float4*)o)[1] = q1;
        }
        if (r1 < nrows) {
            float* o = out + (size_t)r1 * 128 + tc * 8;
            float4 q0, q1;
            q0.x = fmaxf(v1[0] + bb[0], 0.f); q0.y = fmaxf(v1[1] + bb[1], 0.f);
            q0.z = fmaxf(v1[2] + bb[2], 0.f); q0.w = fmaxf(v1[3] + bb[3], 0.f);
            q1.x = fmaxf(v1[4] + bb[4], 0.f); q1.y = fmaxf(v1[5] + bb[5], 0.f);
            q1.z = fmaxf(v1[6] + bb[6], 0.f); q1.w = fmaxf(v1[7] + bb[7], 0.f);
            ((float4*)o)[0] = q0; ((float4*)o)[1] = q1;
        }
    }
}

// ---------------- launch ----------------
extern "C" void kernel_launch(void* const* d_in, const int* in_sizes, int n_in,
                              void* d_out, int out_size) {
    const float* x   = (const float*)d_in[0];
    const int*   ei  = (const int*)  d_in[1];
    const float* Wl1 = (const float*)d_in[2];
    const float* Wr1 = (const float*)d_in[3];
    const float* b1  = (const float*)d_in[4];
    const float* Wl2 = (const float*)d_in[5];
    const float* Wr2 = (const float*)d_in[6];
    const float* b2  = (const float*)d_in[7];
    float* out = (float*)d_out;

    const int E = in_sizes[1] / 2;     // 800000
    const int N = in_sizes[0] / DIN1;  // 50000

    float *agg1, *agg2, *h, *inv, *W1t, *W2t;
    int* cnt;
    cudaGetSymbolAddress((void**)&agg1, g_agg1);
    cudaGetSymbolAddress((void**)&agg2, g_agg2);
    cudaGetSymbolAddress((void**)&h,    g_h);
    cudaGetSymbolAddress((void**)&inv,  g_inv);
    cudaGetSymbolAddress((void**)&cnt,  g_cnt);
    cudaGetSymbolAddress((void**)&W1t,  g_W1t);
    cudaGetSymbolAddress((void**)&W2t,  g_W2t);

    const int SMEM1 = (2 * DIN1 * DH + 16 * 128) * 4;   // 73,728 B
    const int SMEM2 = (2 * DH * DH + 16 * 128) * 4;     // 139,264 B
    cudaFuncSetAttribute(gemm_kernel<2 * DIN1>, cudaFuncAttributeMaxDynamicSharedMemorySize, SMEM1);
    cudaFuncSetAttribute(gemm_kernel<2 * DH>,   cudaFuncAttributeMaxDynamicSharedMemorySize, SMEM2);

    // zero scratch (fixed NN-sized buffers; deterministic)
    zero_kernel<<<(NN * 16 + 255) / 256, 256>>>(g_agg1 ? g_agg1 : g_agg1, 0);  // (unused dummy avoided below)
    // NOTE: use symbol-resolved pointers:
    zero_kernel<<<(NN * 16 + 255) / 256, 256>>>((float4*)agg1, NN * 16);
    zero_kernel<<<(NN * 32 + 255) / 256, 256>>>((float4*)agg2, NN * 32);
    zero_kernel<<<(NN / 4 + 255) / 256, 256>>>((float4*)cnt, NN / 4);

    prep_w<<<(2 * DIN1 * DH + 2 * DH * DH + 255) / 256, 256>>>(Wl1, Wr1, Wl2, Wr2);

    count_kernel<<<(E + 255) / 256, 256>>>(ei + E, cnt, E);
    inv_kernel<<<(N + 255) / 256, 256>>>(cnt, inv, N);

    // layer 1
    scatter_kernel<16><<<(E * 16 + 255) / 256, 256>>>(ei, ei + E, x, agg1, E);
    gemm_kernel<2 * DIN1><<<(N + 127) / 128, 256, SMEM1>>>(agg1, x, W1t, b1, inv, h, N);

    // layer 2
    scatter_kernel<32><<<(E * 32 + 255) / 256, 256>>>(ei, ei + E, h, agg2, E);
    gemm_kernel<2 * DH><<<(N + 127) / 128, 256, SMEM2>>>(agg2, h, W2t, b2, inv, out, N);
}

// round 7
// speedup vs baseline: 1.0919x; 1.0919x over previous
#include <cuda_runtime.h>
#include <cuda_bf16.h>
#include <cstdint>

#define NN 50000
#define EMAX 800000
#define DIN1 64
#define DH 128

// ---------------- scratch (device globals; no allocation allowed) ----------------
__device__ float4 g_agg1[NN * (DIN1 / 4)];        // [NN, 64]  mean-aggregated
__device__ float4 g_h   [NN * (DH   / 4)];        // [NN, 128] layer-1 output
__device__ float4 g_agg2[NN * (DH   / 4)];        // [NN, 128] mean-aggregated
__device__ int    g_cnt [NN];                     // degree histogram
__device__ int    g_offs[NN + 1];                 // CSR row offsets
__device__ int    g_cursor[NN];                   // fill cursors
__device__ int    g_csr [EMAX];                   // CSR column (src) indices
__device__ float4 g_W1t [(2 * DIN1 * DH) / 4];    // k-major combined [128, 128]
__device__ float4 g_W2t [(2 * DH   * DH) / 4];    // k-major combined [256, 128]

// ---------------- helpers ----------------
__device__ __forceinline__ unsigned long long f2ull(float lo, float hi) {
    unsigned long long r;
    asm("mov.b64 %0, {%1, %2};" : "=l"(r) : "f"(lo), "f"(hi));
    return r;
}
__device__ __forceinline__ float2 ull2f(unsigned long long v) {
    float2 r;
    asm("mov.b64 {%0, %1}, %2;" : "=f"(r.x), "=f"(r.y) : "l"(v));
    return r;
}
// packed fp32x2 FMA (Blackwell; 2x FFMA rate, only reachable via PTX)
__device__ __forceinline__ unsigned long long fma2(unsigned long long a,
                                                   unsigned long long b,
                                                   unsigned long long c) {
    unsigned long long d;
    asm("fma.rn.f32x2 %0, %1, %2, %3;" : "=l"(d) : "l"(a), "l"(b), "l"(c));
    return d;
}

// ---------------- tiny prep kernels ----------------
__global__ void zero_kernel(float4* __restrict__ p, int n4) {
    int i = blockIdx.x * blockDim.x + threadIdx.x;
    if (i < n4) p[i] = make_float4(0.f, 0.f, 0.f, 0.f);
}

__global__ void count_kernel(const int* __restrict__ dst, int* __restrict__ cnt, int E) {
    int e = blockIdx.x * blockDim.x + threadIdx.x;
    if (e < E) atomicAdd(&cnt[__ldg(dst + e)], 1);
}

// single-block exclusive scan over cnt -> offs (and cursor copy); offs[N] = total
__global__ void scan_kernel(const int* __restrict__ cnt, int* __restrict__ offs,
                            int* __restrict__ cursor, int N) {
    __shared__ int wsum[32];
    __shared__ int s_carry, s_total;
    const int t = threadIdx.x, lane = t & 31, w = t >> 5;
    if (t == 0) s_carry = 0;
    for (int base = 0; base < N; base += 1024) {
        __syncthreads();                         // carry from previous chunk visible
        int i = base + t;
        int v = (i < N) ? cnt[i] : 0;
        int x = v;
#pragma unroll
        for (int d = 1; d < 32; d <<= 1) {
            int y = __shfl_up_sync(0xffffffffu, x, d);
            if (lane >= d) x += y;
        }
        if (lane == 31) wsum[w] = x;
        __syncthreads();
        if (t < 32) {
            int y = wsum[t], z = y;
#pragma unroll
            for (int d = 1; d < 32; d <<= 1) {
                int u = __shfl_up_sync(0xffffffffu, z, d);
                if (t >= d) z += u;
            }
            wsum[t] = z - y;                     // exclusive warp offset
            if (t == 31) s_total = z;            // chunk total
        }
        __syncthreads();
        int excl = (x - v) + wsum[w] + s_carry;
        if (i < N) { offs[i] = excl; cursor[i] = excl; }
        __syncthreads();
        if (t == 0) s_carry += s_total;
    }
    __syncthreads();
    if (t == 0) offs[N] = s_carry;               // == E
}

__global__ void fill_kernel(const int* __restrict__ src, const int* __restrict__ dst,
                            int* __restrict__ cursor, int* __restrict__ csr, int E) {
    int e = blockIdx.x * blockDim.x + threadIdx.x;
    if (e < E) {
        int d = __ldg(dst + e);
        int p = atomicAdd(&cursor[d], 1);
        csr[p] = __ldg(src + e);
    }
}

// Build k-major combined weights: Wt[k][c] = Wl[c][k] (k<DIN) else Wr[c][k-DIN]
__global__ void prep_w(const float* __restrict__ Wl1, const float* __restrict__ Wr1,
                       const float* __restrict__ Wl2, const float* __restrict__ Wr2) {
    int i = blockIdx.x * blockDim.x + threadIdx.x;
    float* w1 = (float*)g_W1t;
    float* w2 = (float*)g_W2t;
    const int n1 = 2 * DIN1 * DH;   // 16384
    const int n2 = 2 * DH * DH;     // 32768
    if (i < n1) {
        int k = i >> 7, c = i & 127;
        w1[i] = (k < DIN1) ? Wl1[c * DIN1 + k] : Wr1[c * DIN1 + (k - DIN1)];
    } else if (i < n1 + n2) {
        int j = i - n1;
        int k = j >> 7, c = j & 127;
        w2[j] = (k < DH) ? Wl2[c * DH + k] : Wr2[c * DH + (k - DH)];
    }
}

// ---------------- CSR mean-aggregation: agg[n] = mean_{s in nbrs(n)} x[s] ---------
// L float4s per row; a group of L lanes owns one node, each lane one float4 column.
// Gathers are fully coalesced within a row (L*16B contiguous); no atomics, single
// plain store of the mean. Unroll-2 for in-thread MLP.
template <int L>
__global__ void aggregate_kernel(const int* __restrict__ csr, const int* __restrict__ offs,
                                 const float* __restrict__ xin, float* __restrict__ agg,
                                 int N) {
    int g = blockIdx.x * blockDim.x + threadIdx.x;
    int node = g / L, lane = g % L;
    if (node >= N) return;
    int beg = __ldg(offs + node), end = __ldg(offs + node + 1);
    const float4* xi = (const float4*)xin;
    float4 a = make_float4(0.f, 0.f, 0.f, 0.f);
    float4 b = make_float4(0.f, 0.f, 0.f, 0.f);
    int j = beg;
    for (; j + 1 < end; j += 2) {
        int s0 = __ldg(csr + j), s1 = __ldg(csr + j + 1);
        float4 v0 = __ldg(xi + (size_t)s0 * L + lane);
        float4 v1 = __ldg(xi + (size_t)s1 * L + lane);
        a.x += v0.x; a.y += v0.y; a.z += v0.z; a.w += v0.w;
        b.x += v1.x; b.y += v1.y; b.z += v1.z; b.w += v1.w;
    }
    if (j < end) {
        int s0 = __ldg(csr + j);
        float4 v0 = __ldg(xi + (size_t)s0 * L + lane);
        a.x += v0.x; a.y += v0.y; a.z += v0.z; a.w += v0.w;
    }
    int c = end - beg;
    float inv = 1.0f / (float)(c > 0 ? c : 1);
    float4 r;
    r.x = (a.x + b.x) * inv; r.y = (a.y + b.y) * inv;
    r.z = (a.z + b.z) * inv; r.w = (a.w + b.w) * inv;
    ((float4*)agg)[(size_t)node * L + lane] = r;
}

// ---------------- fused GEMM: out = relu([agg | x] @ Wt + b) ----------------------
// K = 2*DIN concat dim. BM=128, BN=128 (full), BK=16, 256 thr, 8x8 microtile.
// Column-pair f32x2 accumulation: packed W operands read directly from SMEM as
// ulonglong2 (zero packing movs); A staged pre-duplicated (a,a) as 64-bit values
// in a stride-130 ull layout (16B-aligned reads, low-conflict stores).
template <int K>
__launch_bounds__(256, 1)
__global__ void gemm_kernel(const float* __restrict__ A,   // [nrows, DIN] mean-agg
                            const float* __restrict__ X,   // [nrows, DIN]
                            const float* __restrict__ Wt, const float* __restrict__ bias,
                            float* __restrict__ out, int nrows) {
    constexpr int DIN = K / 2;
    extern __shared__ float smem[];
    float* sW = smem;                                              // K*128 floats
    unsigned long long* sA = (unsigned long long*)(smem + K * 128); // [16][130] ull
    const int tid = threadIdx.x;

    // stage full weight block (contiguous, coalesced)
    for (int i = tid; i < K * 32; i += 256)
        ((float4*)sW)[i] = ((const float4*)Wt)[i];

    const int rowBase = blockIdx.x * 128;
    const int tc = tid & 15;        // col group: cols tc*8..tc*8+7
    const int tr = tid >> 4;        // row group: rows tr*8..tr*8+7

    unsigned long long acc[8][4];   // [row][col-pair]
#pragma unroll
    for (int r = 0; r < 8; r++)
#pragma unroll
        for (int cp = 0; cp < 4; cp++) acc[r][cp] = 0ull;

    for (int kb = 0; kb < K; kb += 16) {
        // stage A chunk transposed + duplicated: sA[k][row] = (a, a)
#pragma unroll
        for (int j = 0; j < 2; j++) {
            int item = tid + 256 * j;          // 0..511
            int row  = item >> 2;              // 0..127
            int kq   = item & 3;               // which float4 of the 16 k's
            int kg   = kb + kq * 4;
            int rg   = rowBase + row;
            float4 v = make_float4(0.f, 0.f, 0.f, 0.f);
            if (rg < nrows) {
                v = (kg < DIN)
                    ? __ldg((const float4*)(A + (size_t)rg * DIN + kg))
                    : __ldg((const float4*)(X + (size_t)rg * DIN + (kg - DIN)));
            }
            unsigned long long* d = sA + (size_t)(kq * 4) * 130 + row;
            d[0]       = f2ull(v.x, v.x);
            d[130]     = f2ull(v.y, v.y);
            d[260]     = f2ull(v.z, v.z);
            d[390]     = f2ull(v.w, v.w);
        }
        __syncthreads();

#pragma unroll
        for (int k = 0; k < 16; k++) {
            const ulonglong2* ap = (const ulonglong2*)(sA + k * 130 + tr * 8);
            ulonglong2 p0 = ap[0], p1 = ap[1], p2 = ap[2], p3 = ap[3];
            unsigned long long a2[8] = {p0.x, p0.y, p1.x, p1.y, p2.x, p2.y, p3.x, p3.y};
            const ulonglong2* wp = (const ulonglong2*)&sW[(kb + k) * 128 + tc * 8];
            ulonglong2 w01 = wp[0], w23 = wp[1];
            unsigned long long wv[4] = {w01.x, w01.y, w23.x, w23.y};
#pragma unroll
            for (int r = 0; r < 8; r++)
#pragma unroll
                for (int cp = 0; cp < 4; cp++)
                    acc[r][cp] = fma2(a2[r], wv[cp], acc[r][cp]);
        }
        __syncthreads();
    }

    // epilogue: bias + relu + store (acc[r][cp] = cols (tc*8+2cp, tc*8+2cp+1))
    float bb[8];
#pragma unroll
    for (int c = 0; c < 8; c++) bb[c] = __ldg(bias + tc * 8 + c);

#pragma unroll
    for (int r = 0; r < 8; r++) {
        int rg = rowBase + tr * 8 + r;
        if (rg < nrows) {
            float vv[8];
#pragma unroll
            for (int cp = 0; cp < 4; cp++) {
                float2 p = ull2f(acc[r][cp]);
                vv[2 * cp] = p.x; vv[2 * cp + 1] = p.y;
            }
            float* o = out + (size_t)rg * 128 + tc * 8;
            float4 q0, q1;
            q0.x = fmaxf(vv[0] + bb[0], 0.f); q0.y = fmaxf(vv[1] + bb[1], 0.f);
            q0.z = fmaxf(vv[2] + bb[2], 0.f); q0.w = fmaxf(vv[3] + bb[3], 0.f);
            q1.x = fmaxf(vv[4] + bb[4], 0.f); q1.y = fmaxf(vv[5] + bb[5], 0.f);
            q1.z = fmaxf(vv[6] + bb[6], 0.f); q1.w = fmaxf(vv[7] + bb[7], 0.f);
            ((float4*)o)[0] = q0; ((float4*)o)[1] = q1;
        }
    }
}

// ---------------- launch ----------------
extern "C" void kernel_launch(void* const* d_in, const int* in_sizes, int n_in,
                              void* d_out, int out_size) {
    const float* x   = (const float*)d_in[0];
    const int*   ei  = (const int*)  d_in[1];
    const float* Wl1 = (const float*)d_in[2];
    const float* Wr1 = (const float*)d_in[3];
    const float* b1  = (const float*)d_in[4];
    const float* Wl2 = (const float*)d_in[5];
    const float* Wr2 = (const float*)d_in[6];
    const float* b2  = (const float*)d_in[7];
    float* out = (float*)d_out;

    const int E = in_sizes[1] / 2;     // 800000
    const int N = in_sizes[0] / DIN1;  // 50000

    float *agg1, *agg2, *h, *W1t, *W2t;
    int *cnt, *offs, *cursor, *csr;
    cudaGetSymbolAddress((void**)&agg1,   g_agg1);
    cudaGetSymbolAddress((void**)&agg2,   g_agg2);
    cudaGetSymbolAddress((void**)&h,      g_h);
    cudaGetSymbolAddress((void**)&cnt,    g_cnt);
    cudaGetSymbolAddress((void**)&offs,   g_offs);
    cudaGetSymbolAddress((void**)&cursor, g_cursor);
    cudaGetSymbolAddress((void**)&csr,    g_csr);
    cudaGetSymbolAddress((void**)&W1t,    g_W1t);
    cudaGetSymbolAddress((void**)&W2t,    g_W2t);

    const int SMEM1 = 2 * DIN1 * DH * 4 + 16 * 130 * 8;   //  82,176 B
    const int SMEM2 = 2 * DH   * DH * 4 + 16 * 130 * 8;   // 147,712 B
    cudaFuncSetAttribute(gemm_kernel<2 * DIN1>, cudaFuncAttributeMaxDynamicSharedMemorySize, SMEM1);
    cudaFuncSetAttribute(gemm_kernel<2 * DH>,   cudaFuncAttributeMaxDynamicSharedMemorySize, SMEM2);

    // CSR build (shared by both layers; only cnt needs zeroing — agg buffers are
    // fully overwritten by the aggregator, including deg-0 rows)
    zero_kernel<<<(NN / 4 + 255) / 256, 256>>>((float4*)cnt, NN / 4);
    prep_w<<<(2 * DIN1 * DH + 2 * DH * DH + 255) / 256, 256>>>(Wl1, Wr1, Wl2, Wr2);
    count_kernel<<<(E + 255) / 256, 256>>>(ei + E, cnt, E);
    scan_kernel<<<1, 1024>>>(cnt, offs, cursor, N);
    fill_kernel<<<(E + 255) / 256, 256>>>(ei, ei + E, cursor, csr, E);

    // layer 1
    aggregate_kernel<16><<<(N * 16 + 255) / 256, 256>>>(csr, offs, x, agg1, N);
    gemm_kernel<2 * DIN1><<<(N + 127) / 128, 256, SMEM1>>>(agg1, x, W1t, b1, h, N);

    // layer 2
    aggregate_kernel<32><<<(N * 32 + 255) / 256, 256>>>(csr, offs, h, agg2, N);
    gemm_kernel<2 * DH><<<(N + 127) / 128, 256, SMEM2>>>(agg2, h, W2t, b2, out, N);
}

// round 8
// speedup vs baseline: 1.1590x; 1.0614x over previous
#include <cuda_runtime.h>
#include <cuda_bf16.h>
#include <cstdint>

#define NN 50000
#define EMAX 800000
#define DIN1 64
#define DH 128

// ---------------- scratch (device globals; no allocation allowed) ----------------
__device__ float4 g_agg1[NN * (DIN1 / 4)];        // [NN, 64]  mean-aggregated
__device__ float4 g_h   [NN * (DH   / 4)];        // [NN, 128] layer-1 output
__device__ float4 g_agg2[NN * (DH   / 4)];        // [NN, 128] mean-aggregated
__device__ int    g_cnt [NN];                     // degree histogram
__device__ int    g_offs[NN + 1];                 // CSR row offsets
__device__ int    g_cursor[NN];                   // fill cursors
__device__ int    g_csr [EMAX];                   // CSR column (src) indices
__device__ int    g_bsum[128];                    // per-block scan partials
__device__ int    g_boff[128];                    // scanned block offsets
__device__ float4 g_W1t [(2 * DIN1 * DH) / 4];    // k-major combined [128, 128]
__device__ float4 g_W2t [(2 * DH   * DH) / 4];    // k-major combined [256, 128]

// ---------------- helpers ----------------
__device__ __forceinline__ unsigned long long f2ull(float lo, float hi) {
    unsigned long long r;
    asm("mov.b64 %0, {%1, %2};" : "=l"(r) : "f"(lo), "f"(hi));
    return r;
}
__device__ __forceinline__ float2 ull2f(unsigned long long v) {
    float2 r;
    asm("mov.b64 {%0, %1}, %2;" : "=f"(r.x), "=f"(r.y) : "l"(v));
    return r;
}
// packed fp32x2 FMA (Blackwell; 2x FFMA rate, only reachable via PTX)
__device__ __forceinline__ unsigned long long fma2(unsigned long long a,
                                                   unsigned long long b,
                                                   unsigned long long c) {
    unsigned long long d;
    asm("fma.rn.f32x2 %0, %1, %2, %3;" : "=l"(d) : "l"(a), "l"(b), "l"(c));
    return d;
}

// ---------------- tiny prep kernels ----------------
__global__ void zero_kernel(float4* __restrict__ p, int n4) {
    int i = blockIdx.x * blockDim.x + threadIdx.x;
    if (i < n4) p[i] = make_float4(0.f, 0.f, 0.f, 0.f);
}

__global__ void count_kernel(const int* __restrict__ dst, int* __restrict__ cnt, int E) {
    int e = blockIdx.x * blockDim.x + threadIdx.x;
    if (e < E) atomicAdd(&cnt[__ldg(dst + e)], 1);
}

// ---- multi-block scan, phase A: per-block exclusive scan + block total ----------
__global__ void scanA_kernel(const int* __restrict__ cnt, int* __restrict__ offs,
                             int* __restrict__ bsum, int N) {
    __shared__ int wsum[32];
    const int t = threadIdx.x, lane = t & 31, w = t >> 5;
    int i = blockIdx.x * 1024 + t;
    int v = (i < N) ? cnt[i] : 0;
    int x = v;
#pragma unroll
    for (int d = 1; d < 32; d <<= 1) {
        int y = __shfl_up_sync(0xffffffffu, x, d);
        if (lane >= d) x += y;
    }
    if (lane == 31) wsum[w] = x;
    __syncthreads();
    if (t < 32) {
        int y = wsum[t], z = y;
#pragma unroll
        for (int d = 1; d < 32; d <<= 1) {
            int u = __shfl_up_sync(0xffffffffu, z, d);
            if (t >= d) z += u;
        }
        wsum[t] = z - y;                       // exclusive warp offset
        if (t == 31) bsum[blockIdx.x] = z;     // block total
    }
    __syncthreads();
    if (i < N) offs[i] = (x - v) + wsum[w];    // block-local exclusive
}

// ---- phase B: one warp scans the (<=128) block totals (exclusive) --------------
__global__ void scanB_kernel(const int* __restrict__ bsum, int* __restrict__ boff, int nb) {
    const int t = threadIdx.x;                 // 128 threads, 4 warps
    __shared__ int ws[4];
    int v = (t < nb) ? bsum[t] : 0;
    int x = v;
    int lane = t & 31, w = t >> 5;
#pragma unroll
    for (int d = 1; d < 32; d <<= 1) {
        int y = __shfl_up_sync(0xffffffffu, x, d);
        if (lane >= d) x += y;
    }
    if (lane == 31) ws[w] = x;
    __syncthreads();
    int add = 0;
#pragma unroll
    for (int k = 0; k < 4; k++) add += (k < w) ? ws[k] : 0;
    if (t < nb) boff[t] = (x - v) + add;
}

// ---- phase C: apply block offsets, copy to cursor, set offs[N]=E ---------------
__global__ void scanC_kernel(int* __restrict__ offs, int* __restrict__ cursor,
                             const int* __restrict__ boff, int N, int E) {
    int i = blockIdx.x * 1024 + threadIdx.x;
    if (i < N) {
        int o = offs[i] + boff[blockIdx.x];
        offs[i] = o;
        cursor[i] = o;
    } else if (i == N) {
        offs[N] = E;
    }
}

__global__ void fill_kernel(const int* __restrict__ src, const int* __restrict__ dst,
                            int* __restrict__ cursor, int* __restrict__ csr, int E) {
    int e = blockIdx.x * blockDim.x + threadIdx.x;
    if (e < E) {
        int d = __ldg(dst + e);
        int p = atomicAdd(&cursor[d], 1);
        csr[p] = __ldg(src + e);
    }
}

// Build k-major combined weights: Wt[k][c] = Wl[c][k] (k<DIN) else Wr[c][k-DIN]
__global__ void prep_w(const float* __restrict__ Wl1, const float* __restrict__ Wr1,
                       const float* __restrict__ Wl2, const float* __restrict__ Wr2) {
    int i = blockIdx.x * blockDim.x + threadIdx.x;
    float* w1 = (float*)g_W1t;
    float* w2 = (float*)g_W2t;
    const int n1 = 2 * DIN1 * DH;   // 16384
    const int n2 = 2 * DH * DH;     // 32768
    if (i < n1) {
        int k = i >> 7, c = i & 127;
        w1[i] = (k < DIN1) ? Wl1[c * DIN1 + k] : Wr1[c * DIN1 + (k - DIN1)];
    } else if (i < n1 + n2) {
        int j = i - n1;
        int k = j >> 7, c = j & 127;
        w2[j] = (k < DH) ? Wl2[c * DH + k] : Wr2[c * DH + (k - DH)];
    }
}

// ---------------- CSR mean-aggregation: agg[n] = mean_{s in nbrs(n)} x[s] ---------
// L float4s per row; a group of L lanes owns one node, each lane one float4 column.
// Coalesced gathers, no atomics, one plain store. Unroll-4 for MLP=4 (hides the
// ~250cyc L2 latency alongside high warp occupancy).
template <int L>
__global__ void aggregate_kernel(const int* __restrict__ csr, const int* __restrict__ offs,
                                 const float* __restrict__ xin, float* __restrict__ agg,
                                 int N) {
    int g = blockIdx.x * blockDim.x + threadIdx.x;
    int node = g / L, lane = g % L;
    if (node >= N) return;
    int beg = __ldg(offs + node), end = __ldg(offs + node + 1);
    const float4* xi = (const float4*)xin;
    float4 a = make_float4(0.f, 0.f, 0.f, 0.f);
    float4 b = make_float4(0.f, 0.f, 0.f, 0.f);
    float4 c4 = make_float4(0.f, 0.f, 0.f, 0.f);
    float4 d4 = make_float4(0.f, 0.f, 0.f, 0.f);
    int j = beg;
    for (; j + 3 < end; j += 4) {
        int s0 = __ldg(csr + j),     s1 = __ldg(csr + j + 1);
        int s2 = __ldg(csr + j + 2), s3 = __ldg(csr + j + 3);
        float4 v0 = __ldg(xi + (size_t)s0 * L + lane);
        float4 v1 = __ldg(xi + (size_t)s1 * L + lane);
        float4 v2 = __ldg(xi + (size_t)s2 * L + lane);
        float4 v3 = __ldg(xi + (size_t)s3 * L + lane);
        a.x += v0.x; a.y += v0.y; a.z += v0.z; a.w += v0.w;
        b.x += v1.x; b.y += v1.y; b.z += v1.z; b.w += v1.w;
        c4.x += v2.x; c4.y += v2.y; c4.z += v2.z; c4.w += v2.w;
        d4.x += v3.x; d4.y += v3.y; d4.z += v3.z; d4.w += v3.w;
    }
    for (; j < end; j++) {
        int s0 = __ldg(csr + j);
        float4 v0 = __ldg(xi + (size_t)s0 * L + lane);
        a.x += v0.x; a.y += v0.y; a.z += v0.z; a.w += v0.w;
    }
    int c = end - beg;
    float inv = 1.0f / (float)(c > 0 ? c : 1);
    float4 r;
    r.x = (a.x + b.x + c4.x + d4.x) * inv;
    r.y = (a.y + b.y + c4.y + d4.y) * inv;
    r.z = (a.z + b.z + c4.z + d4.z) * inv;
    r.w = (a.w + b.w + c4.w + d4.w) * inv;
    ((float4*)agg)[(size_t)node * L + lane] = r;
}

// ---------------- fused GEMM: out = relu([agg | x] @ Wt + b) ----------------------
// K = 2*DIN concat dim. BM=128, BN=128 (full), BK=16, 256 thr, 8x8 microtile.
// Column-pair f32x2 accumulation: packed W operands read directly from SMEM as
// ulonglong2 (zero packing movs); A staged pre-duplicated (a,a) as 64-bit values
// in a stride-130 ull layout (16B-aligned reads, low-conflict stores).
template <int K>
__launch_bounds__(256, 1)
__global__ void gemm_kernel(const float* __restrict__ A,   // [nrows, DIN] mean-agg
                            const float* __restrict__ X,   // [nrows, DIN]
                            const float* __restrict__ Wt, const float* __restrict__ bias,
                            float* __restrict__ out, int nrows) {
    constexpr int DIN = K / 2;
    extern __shared__ float smem[];
    float* sW = smem;                                              // K*128 floats
    unsigned long long* sA = (unsigned long long*)(smem + K * 128); // [16][130] ull
    const int tid = threadIdx.x;

    // stage full weight block (contiguous, coalesced)
    for (int i = tid; i < K * 32; i += 256)
        ((float4*)sW)[i] = ((const float4*)Wt)[i];

    const int rowBase = blockIdx.x * 128;
    const int tc = tid & 15;        // col group: cols tc*8..tc*8+7
    const int tr = tid >> 4;        // row group: rows tr*8..tr*8+7

    unsigned long long acc[8][4];   // [row][col-pair]
#pragma unroll
    for (int r = 0; r < 8; r++)
#pragma unroll
        for (int cp = 0; cp < 4; cp++) acc[r][cp] = 0ull;

    for (int kb = 0; kb < K; kb += 16) {
        // stage A chunk transposed + duplicated: sA[k][row] = (a, a)
#pragma unroll
        for (int j = 0; j < 2; j++) {
            int item = tid + 256 * j;          // 0..511
            int row  = item >> 2;              // 0..127
            int kq   = item & 3;               // which float4 of the 16 k's
            int kg   = kb + kq * 4;
            int rg   = rowBase + row;
            float4 v = make_float4(0.f, 0.f, 0.f, 0.f);
            if (rg < nrows) {
                v = (kg < DIN)
                    ? __ldg((const float4*)(A + (size_t)rg * DIN + kg))
                    : __ldg((const float4*)(X + (size_t)rg * DIN + (kg - DIN)));
            }
            unsigned long long* d = sA + (size_t)(kq * 4) * 130 + row;
            d[0]       = f2ull(v.x, v.x);
            d[130]     = f2ull(v.y, v.y);
            d[260]     = f2ull(v.z, v.z);
            d[390]     = f2ull(v.w, v.w);
        }
        __syncthreads();

#pragma unroll
        for (int k = 0; k < 16; k++) {
            const ulonglong2* ap = (const ulonglong2*)(sA + k * 130 + tr * 8);
            ulonglong2 p0 = ap[0], p1 = ap[1], p2 = ap[2], p3 = ap[3];
            unsigned long long a2[8] = {p0.x, p0.y, p1.x, p1.y, p2.x, p2.y, p3.x, p3.y};
            const ulonglong2* wp = (const ulonglong2*)&sW[(kb + k) * 128 + tc * 8];
            ulonglong2 w01 = wp[0], w23 = wp[1];
            unsigned long long wv[4] = {w01.x, w01.y, w23.x, w23.y};
#pragma unroll
            for (int r = 0; r < 8; r++)
#pragma unroll
                for (int cp = 0; cp < 4; cp++)
                    acc[r][cp] = fma2(a2[r], wv[cp], acc[r][cp]);
        }
        __syncthreads();
    }

    // epilogue: bias + relu + store (acc[r][cp] = cols (tc*8+2cp, tc*8+2cp+1))
    float bb[8];
#pragma unroll
    for (int c = 0; c < 8; c++) bb[c] = __ldg(bias + tc * 8 + c);

#pragma unroll
    for (int r = 0; r < 8; r++) {
        int rg = rowBase + tr * 8 + r;
        if (rg < nrows) {
            float vv[8];
#pragma unroll
            for (int cp = 0; cp < 4; cp++) {
                float2 p = ull2f(acc[r][cp]);
                vv[2 * cp] = p.x; vv[2 * cp + 1] = p.y;
            }
            float* o = out + (size_t)rg * 128 + tc * 8;
            float4 q0, q1;
            q0.x = fmaxf(vv[0] + bb[0], 0.f); q0.y = fmaxf(vv[1] + bb[1], 0.f);
            q0.z = fmaxf(vv[2] + bb[2], 0.f); q0.w = fmaxf(vv[3] + bb[3], 0.f);
            q1.x = fmaxf(vv[4] + bb[4], 0.f); q1.y = fmaxf(vv[5] + bb[5], 0.f);
            q1.z = fmaxf(vv[6] + bb[6], 0.f); q1.w = fmaxf(vv[7] + bb[7], 0.f);
            ((float4*)o)[0] = q0; ((float4*)o)[1] = q1;
        }
    }
}

// ---------------- launch ----------------
extern "C" void kernel_launch(void* const* d_in, const int* in_sizes, int n_in,
                              void* d_out, int out_size) {
    const float* x   = (const float*)d_in[0];
    const int*   ei  = (const int*)  d_in[1];
    const float* Wl1 = (const float*)d_in[2];
    const float* Wr1 = (const float*)d_in[3];
    const float* b1  = (const float*)d_in[4];
    const float* Wl2 = (const float*)d_in[5];
    const float* Wr2 = (const float*)d_in[6];
    const float* b2  = (const float*)d_in[7];
    float* out = (float*)d_out;

    const int E = in_sizes[1] / 2;     // 800000
    const int N = in_sizes[0] / DIN1;  // 50000

    float *agg1, *agg2, *h, *W1t, *W2t;
    int *cnt, *offs, *cursor, *csr, *bsum, *boff;
    cudaGetSymbolAddress((void**)&agg1,   g_agg1);
    cudaGetSymbolAddress((void**)&agg2,   g_agg2);
    cudaGetSymbolAddress((void**)&h,      g_h);
    cudaGetSymbolAddress((void**)&cnt,    g_cnt);
    cudaGetSymbolAddress((void**)&offs,   g_offs);
    cudaGetSymbolAddress((void**)&cursor, g_cursor);
    cudaGetSymbolAddress((void**)&csr,    g_csr);
    cudaGetSymbolAddress((void**)&bsum,   g_bsum);
    cudaGetSymbolAddress((void**)&boff,   g_boff);
    cudaGetSymbolAddress((void**)&W1t,    g_W1t);
    cudaGetSymbolAddress((void**)&W2t,    g_W2t);

    const int SMEM1 = 2 * DIN1 * DH * 4 + 16 * 130 * 8;   //  82,176 B
    const int SMEM2 = 2 * DH   * DH * 4 + 16 * 130 * 8;   // 147,712 B
    cudaFuncSetAttribute(gemm_kernel<2 * DIN1>, cudaFuncAttributeMaxDynamicSharedMemorySize, SMEM1);
    cudaFuncSetAttribute(gemm_kernel<2 * DH>,   cudaFuncAttributeMaxDynamicSharedMemorySize, SMEM2);

    const int NB = (N + 1023) / 1024;  // 49 scan blocks

    // CSR build (shared by both layers)
    zero_kernel<<<(NN / 4 + 255) / 256, 256>>>((float4*)cnt, NN / 4);
    prep_w<<<(2 * DIN1 * DH + 2 * DH * DH + 255) / 256, 256>>>(Wl1, Wr1, Wl2, Wr2);
    count_kernel<<<(E + 255) / 256, 256>>>(ei + E, cnt, E);
    scanA_kernel<<<NB, 1024>>>(cnt, offs, bsum, N);
    scanB_kernel<<<1, 128>>>(bsum, boff, NB);
    scanC_kernel<<<NB + 1, 1024>>>(offs, cursor, boff, N, E);   // +1 covers i==N
    fill_kernel<<<(E + 255) / 256, 256>>>(ei, ei + E, cursor, csr, E);

    // layer 1
    aggregate_kernel<16><<<(N * 16 + 255) / 256, 256>>>(csr, offs, x, agg1, N);
    gemm_kernel<2 * DIN1><<<(N + 127) / 128, 256, SMEM1>>>(agg1, x, W1t, b1, h, N);

    // layer 2
    aggregate_kernel<32><<<(N * 32 + 255) / 256, 256>>>(csr, offs, h, agg2, N);
    gemm_kernel<2 * DH><<<(N + 127) / 128, 256, SMEM2>>>(agg2, h, W2t, b2, out, N);
}

// round 11
// speedup vs baseline: 1.2191x; 1.0519x over previous
#include <cuda_runtime.h>
#include <cuda_bf16.h>
#include <cstdint>

#define NN 50000
#define EMAX 800000
#define DIN1 64
#define DH 128

// ---------------- scratch (device globals; no allocation allowed) ----------------
__device__ float4 g_agg1[NN * (DIN1 / 4)];        // [NN, 64]  mean-aggregated
__device__ float4 g_h   [NN * (DH   / 4)];        // [NN, 128] layer-1 output
__device__ float4 g_agg2[NN * (DH   / 4)];        // [NN, 128] mean-aggregated
__device__ int    g_cnt [NN];                     // degree histogram
__device__ int    g_offs[NN + 1];                 // CSR row offsets
__device__ int    g_cursor[NN];                   // fill cursors
__device__ int    g_csr [EMAX];                   // CSR column (src) indices
__device__ int    g_bsum[128];                    // per-block scan partials
__device__ float4 g_W1t [(2 * DIN1 * DH) / 4];    // k-major combined [128, 128]
__device__ float4 g_W2t [(2 * DH   * DH) / 4];    // k-major combined [256, 128]

// ---------------- helpers ----------------
__device__ __forceinline__ unsigned long long f2ull(float lo, float hi) {
    unsigned long long r;
    asm("mov.b64 %0, {%1, %2};" : "=l"(r) : "f"(lo), "f"(hi));
    return r;
}
__device__ __forceinline__ float2 ull2f(unsigned long long v) {
    float2 r;
    asm("mov.b64 {%0, %1}, %2;" : "=f"(r.x), "=f"(r.y) : "l"(v));
    return r;
}
// packed fp32x2 FMA (Blackwell; 2x FFMA rate, only reachable via PTX)
__device__ __forceinline__ unsigned long long fma2(unsigned long long a,
                                                   unsigned long long b,
                                                   unsigned long long c) {
    unsigned long long d;
    asm("fma.rn.f32x2 %0, %1, %2, %3;" : "=l"(d) : "l"(a), "l"(b), "l"(c));
    return d;
}

// ---------------- fused prep: zero cnt + build k-major combined weights ----------
__global__ void prep_kernel(const float* __restrict__ Wl1, const float* __restrict__ Wr1,
                            const float* __restrict__ Wl2, const float* __restrict__ Wr2) {
    int i = blockIdx.x * blockDim.x + threadIdx.x;
    const int n0 = NN;                  // zero cnt
    const int n1 = 2 * DIN1 * DH;       // 16384
    const int n2 = 2 * DH * DH;         // 32768
    if (i < n0) {
        g_cnt[i] = 0;
    } else if (i < n0 + n1) {
        int j = i - n0;
        int k = j >> 7, c = j & 127;
        ((float*)g_W1t)[j] = (k < DIN1) ? Wl1[c * DIN1 + k] : Wr1[c * DIN1 + (k - DIN1)];
    } else if (i < n0 + n1 + n2) {
        int j = i - n0 - n1;
        int k = j >> 7, c = j & 127;
        ((float*)g_W2t)[j] = (k < DH) ? Wl2[c * DH + k] : Wr2[c * DH + (k - DH)];
    }
}

__global__ void count_kernel(const int* __restrict__ dst, int* __restrict__ cnt, int E) {
    int e = blockIdx.x * blockDim.x + threadIdx.x;
    if (e < E) atomicAdd(&cnt[__ldg(dst + e)], 1);
}

// ---- scan phase A: per-block exclusive scan + block total ----------------------
__global__ void scanA_kernel(const int* __restrict__ cnt, int* __restrict__ offs,
                             int* __restrict__ bsum, int N) {
    __shared__ int wsum[32];
    const int t = threadIdx.x, lane = t & 31, w = t >> 5;
    int i = blockIdx.x * 1024 + t;
    int v = (i < N) ? cnt[i] : 0;
    int x = v;
#pragma unroll
    for (int d = 1; d < 32; d <<= 1) {
        int y = __shfl_up_sync(0xffffffffu, x, d);
        if (lane >= d) x += y;
    }
    if (lane == 31) wsum[w] = x;
    __syncthreads();
    if (t < 32) {
        int y = wsum[t], z = y;
#pragma unroll
        for (int d = 1; d < 32; d <<= 1) {
            int u = __shfl_up_sync(0xffffffffu, z, d);
            if (t >= d) z += u;
        }
        wsum[t] = z - y;                       // exclusive warp offset
        if (t == 31) bsum[blockIdx.x] = z;     // block total
    }
    __syncthreads();
    if (i < N) offs[i] = (x - v) + wsum[w];    // block-local exclusive
}

// ---- scan phase C (B folded in): each block reduces bsum[0..bid) itself --------
// FIX vs last round: each of 64 reducer threads contributes ONLY bsum[t] (t < bid);
// previous version also added bsum[t+32], double-counting bsum[32..63] and pushing
// cursors past EMAX (the source of the illegal access). NB <= 64 is required.
__global__ void scanC_kernel(int* __restrict__ offs, int* __restrict__ cursor,
                             const int* __restrict__ bsum, int N, int E) {
    __shared__ int s_off;
    const int t = threadIdx.x;
    if (t == 0) s_off = 0;
    __syncthreads();
    if (t < 64) {
        int s = (t < blockIdx.x) ? bsum[t] : 0;
#pragma unroll
        for (int d = 16; d > 0; d >>= 1)
            s += __shfl_down_sync(0xffffffffu, s, d);
        if ((t & 31) == 0) atomicAdd(&s_off, s);   // two warp partials
    }
    __syncthreads();
    int i = blockIdx.x * 1024 + t;
    if (i < N) {
        int o = offs[i] + s_off;
        offs[i] = o;
        cursor[i] = o;
    }
    if (blockIdx.x == 0 && t == 0) offs[N] = E;
}

__global__ void fill_kernel(const int* __restrict__ src, const int* __restrict__ dst,
                            int* __restrict__ cursor, int* __restrict__ csr, int E) {
    int e = blockIdx.x * blockDim.x + threadIdx.x;
    if (e < E) {
        int d = __ldg(dst + e);
        int p = atomicAdd(&cursor[d], 1);
        csr[p] = __ldg(src + e);
    }
}

// ---------------- CSR mean-aggregation: agg[n] = mean_{s in nbrs(n)} x[s] ---------
// L float4s per row; group of L lanes owns one node, each lane one float4 column.
// Coalesced gathers, no atomics, one plain store. Unroll-2 (unroll-4 regressed via
// cross-CTA L1tex-queue contention; the kernel is L2-BW-bound, TLP covers latency).
template <int L>
__global__ void aggregate_kernel(const int* __restrict__ csr, const int* __restrict__ offs,
                                 const float* __restrict__ xin, float* __restrict__ agg,
                                 int N) {
    int g = blockIdx.x * blockDim.x + threadIdx.x;
    int node = g / L, lane = g % L;
    if (node >= N) return;
    int beg = __ldg(offs + node), end = __ldg(offs + node + 1);
    const float4* xi = (const float4*)xin;
    float4 a = make_float4(0.f, 0.f, 0.f, 0.f);
    float4 b = make_float4(0.f, 0.f, 0.f, 0.f);
    int j = beg;
    for (; j + 1 < end; j += 2) {
        int s0 = __ldg(csr + j), s1 = __ldg(csr + j + 1);
        float4 v0 = __ldg(xi + (size_t)s0 * L + lane);
        float4 v1 = __ldg(xi + (size_t)s1 * L + lane);
        a.x += v0.x; a.y += v0.y; a.z += v0.z; a.w += v0.w;
        b.x += v1.x; b.y += v1.y; b.z += v1.z; b.w += v1.w;
    }
    if (j < end) {
        int s0 = __ldg(csr + j);
        float4 v0 = __ldg(xi + (size_t)s0 * L + lane);
        a.x += v0.x; a.y += v0.y; a.z += v0.z; a.w += v0.w;
    }
    int c = end - beg;
    float inv = 1.0f / (float)(c > 0 ? c : 1);
    float4 r;
    r.x = (a.x + b.x) * inv; r.y = (a.y + b.y) * inv;
    r.z = (a.z + b.z) * inv; r.w = (a.w + b.w) * inv;
    ((float4*)agg)[(size_t)node * L + lane] = r;
}

// ---------------- persistent fused GEMM: out = relu([agg | x] @ Wt + b) -----------
// K = 2*DIN concat dim. Grid = 148 persistent blocks; W staged ONCE per SM, then
// loop over 128-row tiles. BN=128 (full), BK=16, 256 thr, 8x8 microtile.
// Column-pair f32x2 accumulation; A staged pre-duplicated (a,a) stride-130 ull.
template <int K>
__launch_bounds__(256, 1)
__global__ void gemm_kernel(const float* __restrict__ A,   // [nrows, DIN] mean-agg
                            const float* __restrict__ X,   // [nrows, DIN]
                            const float* __restrict__ Wt, const float* __restrict__ bias,
                            float* __restrict__ out, int nrows, int ntiles) {
    constexpr int DIN = K / 2;
    extern __shared__ float smem[];
    float* sW = smem;                                              // K*128 floats
    unsigned long long* sA = (unsigned long long*)(smem + K * 128); // [16][130] ull
    const int tid = threadIdx.x;

    // stage full weight block once (contiguous, coalesced)
    for (int i = tid; i < K * 32; i += 256)
        ((float4*)sW)[i] = ((const float4*)Wt)[i];

    const int tc = tid & 15;        // col group: cols tc*8..tc*8+7
    const int tr = tid >> 4;        // row group: rows tr*8..tr*8+7

    float bb[8];
#pragma unroll
    for (int c = 0; c < 8; c++) bb[c] = __ldg(bias + tc * 8 + c);

    for (int tile = blockIdx.x; tile < ntiles; tile += gridDim.x) {
        const int rowBase = tile * 128;

        unsigned long long acc[8][4];   // [row][col-pair]
#pragma unroll
        for (int r = 0; r < 8; r++)
#pragma unroll
            for (int cp = 0; cp < 4; cp++) acc[r][cp] = 0ull;

        for (int kb = 0; kb < K; kb += 16) {
            // stage A chunk transposed + duplicated: sA[k][row] = (a, a)
#pragma unroll
            for (int j = 0; j < 2; j++) {
                int item = tid + 256 * j;          // 0..511
                int row  = item >> 2;              // 0..127
                int kq   = item & 3;               // which float4 of the 16 k's
                int kg   = kb + kq * 4;
                int rg   = rowBase + row;
                float4 v = make_float4(0.f, 0.f, 0.f, 0.f);
                if (rg < nrows) {
                    v = (kg < DIN)
                        ? __ldg((const float4*)(A + (size_t)rg * DIN + kg))
                        : __ldg((const float4*)(X + (size_t)rg * DIN + (kg - DIN)));
                }
                unsigned long long* d = sA + (size_t)(kq * 4) * 130 + row;
                d[0]   = f2ull(v.x, v.x);
                d[130] = f2ull(v.y, v.y);
                d[260] = f2ull(v.z, v.z);
                d[390] = f2ull(v.w, v.w);
            }
            __syncthreads();

#pragma unroll
            for (int k = 0; k < 16; k++) {
                const ulonglong2* ap = (const ulonglong2*)(sA + k * 130 + tr * 8);
                ulonglong2 p0 = ap[0], p1 = ap[1], p2 = ap[2], p3 = ap[3];
                unsigned long long a2[8] = {p0.x, p0.y, p1.x, p1.y, p2.x, p2.y, p3.x, p3.y};
                const ulonglong2* wp = (const ulonglong2*)&sW[(kb + k) * 128 + tc * 8];
                ulonglong2 w01 = wp[0], w23 = wp[1];
                unsigned long long wv[4] = {w01.x, w01.y, w23.x, w23.y};
#pragma unroll
                for (int r = 0; r < 8; r++)
#pragma unroll
                    for (int cp = 0; cp < 4; cp++)
                        acc[r][cp] = fma2(a2[r], wv[cp], acc[r][cp]);
            }
            __syncthreads();
        }

        // epilogue: bias + relu + store (regs only; no smem — safe vs next staging)
#pragma unroll
        for (int r = 0; r < 8; r++) {
            int rg = rowBase + tr * 8 + r;
            if (rg < nrows) {
                float vv[8];
#pragma unroll
                for (int cp = 0; cp < 4; cp++) {
                    float2 p = ull2f(acc[r][cp]);
                    vv[2 * cp] = p.x; vv[2 * cp + 1] = p.y;
                }
                float* o = out + (size_t)rg * 128 + tc * 8;
                float4 q0, q1;
                q0.x = fmaxf(vv[0] + bb[0], 0.f); q0.y = fmaxf(vv[1] + bb[1], 0.f);
                q0.z = fmaxf(vv[2] + bb[2], 0.f); q0.w = fmaxf(vv[3] + bb[3], 0.f);
                q1.x = fmaxf(vv[4] + bb[4], 0.f); q1.y = fmaxf(vv[5] + bb[5], 0.f);
                q1.z = fmaxf(vv[6] + bb[6], 0.f); q1.w = fmaxf(vv[7] + bb[7], 0.f);
                ((float4*)o)[0] = q0; ((float4*)o)[1] = q1;
            }
        }
    }
}

// ---------------- launch ----------------
extern "C" void kernel_launch(void* const* d_in, const int* in_sizes, int n_in,
                              void* d_out, int out_size) {
    const float* x   = (const float*)d_in[0];
    const int*   ei  = (const int*)  d_in[1];
    const float* Wl1 = (const float*)d_in[2];
    const float* Wr1 = (const float*)d_in[3];
    const float* b1  = (const float*)d_in[4];
    const float* Wl2 = (const float*)d_in[5];
    const float* Wr2 = (const float*)d_in[6];
    const float* b2  = (const float*)d_in[7];
    float* out = (float*)d_out;

    const int E = in_sizes[1] / 2;     // 800000
    const int N = in_sizes[0] / DIN1;  // 50000

    float *agg1, *agg2, *h, *W1t, *W2t;
    int *cnt, *offs, *cursor, *csr, *bsum;
    cudaGetSymbolAddress((void**)&agg1,   g_agg1);
    cudaGetSymbolAddress((void**)&agg2,   g_agg2);
    cudaGetSymbolAddress((void**)&h,      g_h);
    cudaGetSymbolAddress((void**)&cnt,    g_cnt);
    cudaGetSymbolAddress((void**)&offs,   g_offs);
    cudaGetSymbolAddress((void**)&cursor, g_cursor);
    cudaGetSymbolAddress((void**)&csr,    g_csr);
    cudaGetSymbolAddress((void**)&bsum,   g_bsum);
    cudaGetSymbolAddress((void**)&W1t,    g_W1t);
    cudaGetSymbolAddress((void**)&W2t,    g_W2t);

    const int SMEM1 = 2 * DIN1 * DH * 4 + 16 * 130 * 8;   //  82,176 B
    const int SMEM2 = 2 * DH   * DH * 4 + 16 * 130 * 8;   // 147,712 B
    cudaFuncSetAttribute(gemm_kernel<2 * DIN1>, cudaFuncAttributeMaxDynamicSharedMemorySize, SMEM1);
    cudaFuncSetAttribute(gemm_kernel<2 * DH>,   cudaFuncAttributeMaxDynamicSharedMemorySize, SMEM2);

    const int NB = (N + 1023) / 1024;       // 49 scan blocks (must be <= 64)
    const int NT = (N + 127) / 128;         // 391 GEMM row tiles
    const int PREP = NN + 2 * DIN1 * DH + 2 * DH * DH;

    // CSR build (shared by both layers)
    prep_kernel<<<(PREP + 255) / 256, 256>>>(Wl1, Wr1, Wl2, Wr2);
    count_kernel<<<(E + 255) / 256, 256>>>(ei + E, cnt, E);
    scanA_kernel<<<NB, 1024>>>(cnt, offs, bsum, N);
    scanC_kernel<<<NB, 1024>>>(offs, cursor, bsum, N, E);
    fill_kernel<<<(E + 255) / 256, 256>>>(ei, ei + E, cursor, csr, E);

    // layer 1
    aggregate_kernel<16><<<(N * 16 + 255) / 256, 256>>>(csr, offs, x, agg1, N);
    gemm_kernel<2 * DIN1><<<148, 256, SMEM1>>>(agg1, x, W1t, b1, h, N, NT);

    // layer 2
    aggregate_kernel<32><<<(N * 32 + 255) / 256, 256>>>(csr, offs, h, agg2, N);
    gemm_kernel<2 * DH><<<148, 256, SMEM2>>>(agg2, h, W2t, b2, out, N, NT);
}

// round 13
// speedup vs baseline: 1.7016x; 1.3957x over previous
#include <cuda_runtime.h>
#include <cuda_bf16.h>
#include <cstdint>

#define NN 50000
#define EMAX 800000
#define DIN1 64
#define DH 128

// ---------------- scratch (device globals; no allocation allowed) ----------------
__device__ __nv_bfloat16 g_xh [NN * DIN1], g_xl [NN * DIN1];   // x split
__device__ __nv_bfloat16 g_a1h[NN * DIN1], g_a1l[NN * DIN1];   // agg1 split
__device__ float4        g_h4 [NN * (DH / 4)];                 // h fp32 (agg2 input)
__device__ __nv_bfloat16 g_hh [NN * DH],   g_hl [NN * DH];     // h split
__device__ __nv_bfloat16 g_a2h[NN * DH],   g_a2l[NN * DH];     // agg2 split
__device__ __nv_bfloat16 g_B1h[DH * 2 * DIN1], g_B1l[DH * 2 * DIN1]; // [128,128] n-major
__device__ __nv_bfloat16 g_B2h[DH * 2 * DH],   g_B2l[DH * 2 * DH];   // [128,256] n-major
__device__ int g_cnt[NN], g_offs[NN + 1], g_cursor[NN], g_csr[EMAX], g_bsum[128];

// bf16x2 MMA via the baseline (sm_80+) path — compiles for plain sm_103 target.
#define MMA_BF16(c, a, b0, b1)                                               \
    asm volatile(                                                            \
        "mma.sync.aligned.m16n8k16.row.col.f32.bf16.bf16.f32 "               \
        "{%0,%1,%2,%3}, {%4,%5,%6,%7}, {%8,%9}, {%0,%1,%2,%3};"              \
        : "+f"((c)[0]), "+f"((c)[1]), "+f"((c)[2]), "+f"((c)[3])             \
        : "r"((a)[0]), "r"((a)[1]), "r"((a)[2]), "r"((a)[3]),                \
          "r"(b0), "r"(b1))

// ---------------- prep: zero cnt + split x + build B(hi/lo) ----------------------
__global__ void prep_kernel(const float* __restrict__ x,
                            const float* __restrict__ Wl1, const float* __restrict__ Wr1,
                            const float* __restrict__ Wl2, const float* __restrict__ Wr2) {
    int i = blockIdx.x * blockDim.x + threadIdx.x;
    const int n0 = NN;
    const int n1 = NN * DIN1;        // x split
    const int n2 = 128 * 128;        // B1
    const int n3 = 128 * 256;        // B2
    if (i < n0) {
        g_cnt[i] = 0;
    } else if (i < n0 + n1) {
        int j = i - n0;
        float v = x[j];
        unsigned u = __float_as_uint(v);
        ((unsigned short*)g_xh)[j] = (unsigned short)(u >> 16);
        g_xl[j] = __float2bfloat16_rn(v - __uint_as_float(u & 0xFFFF0000u));
    } else if (i < n0 + n1 + n2) {
        int j = i - n0 - n1;
        int n = j >> 7, k = j & 127;
        float v = (k < DIN1) ? Wl1[n * DIN1 + k] : Wr1[n * DIN1 + (k - DIN1)];
        unsigned u = __float_as_uint(v);
        ((unsigned short*)g_B1h)[j] = (unsigned short)(u >> 16);
        g_B1l[j] = __float2bfloat16_rn(v - __uint_as_float(u & 0xFFFF0000u));
    } else if (i < n0 + n1 + n2 + n3) {
        int j = i - n0 - n1 - n2;
        int n = j >> 8, k = j & 255;
        float v = (k < DH) ? Wl2[n * DH + k] : Wr2[n * DH + (k - DH)];
        unsigned u = __float_as_uint(v);
        ((unsigned short*)g_B2h)[j] = (unsigned short)(u >> 16);
        g_B2l[j] = __float2bfloat16_rn(v - __uint_as_float(u & 0xFFFF0000u));
    }
}

__global__ void count_kernel(const int* __restrict__ dst, int* __restrict__ cnt, int E) {
    int e = blockIdx.x * blockDim.x + threadIdx.x;
    if (e < E) atomicAdd(&cnt[__ldg(dst + e)], 1);
}

__global__ void scanA_kernel(const int* __restrict__ cnt, int* __restrict__ offs,
                             int* __restrict__ bsum, int N) {
    __shared__ int wsum[32];
    const int t = threadIdx.x, lane = t & 31, w = t >> 5;
    int i = blockIdx.x * 1024 + t;
    int v = (i < N) ? cnt[i] : 0;
    int x = v;
#pragma unroll
    for (int d = 1; d < 32; d <<= 1) {
        int y = __shfl_up_sync(0xffffffffu, x, d);
        if (lane >= d) x += y;
    }
    if (lane == 31) wsum[w] = x;
    __syncthreads();
    if (t < 32) {
        int y = wsum[t], z = y;
#pragma unroll
        for (int d = 1; d < 32; d <<= 1) {
            int u = __shfl_up_sync(0xffffffffu, z, d);
            if (t >= d) z += u;
        }
        wsum[t] = z - y;
        if (t == 31) bsum[blockIdx.x] = z;
    }
    __syncthreads();
    if (i < N) offs[i] = (x - v) + wsum[w];
}

__global__ void scanC_kernel(int* __restrict__ offs, int* __restrict__ cursor,
                             const int* __restrict__ bsum, int N, int E) {
    __shared__ int s_off;
    const int t = threadIdx.x;
    if (t == 0) s_off = 0;
    __syncthreads();
    if (t < 64) {
        int s = (t < blockIdx.x) ? bsum[t] : 0;
#pragma unroll
        for (int d = 16; d > 0; d >>= 1)
            s += __shfl_down_sync(0xffffffffu, s, d);
        if ((t & 31) == 0) atomicAdd(&s_off, s);
    }
    __syncthreads();
    int i = blockIdx.x * 1024 + t;
    if (i < N) {
        int o = offs[i] + s_off;
        offs[i] = o;
        cursor[i] = o;
    }
    if (blockIdx.x == 0 && t == 0) offs[N] = E;
}

__global__ void fill_kernel(const int* __restrict__ src, const int* __restrict__ dst,
                            int* __restrict__ cursor, int* __restrict__ csr, int E) {
    int e = blockIdx.x * blockDim.x + threadIdx.x;
    if (e < E) {
        int d = __ldg(dst + e);
        int p = atomicAdd(&cursor[d], 1);
        csr[p] = __ldg(src + e);
    }
}

// ---------------- CSR mean-aggregation -> split bf16 output ----------------------
template <int L>
__global__ void aggregate_kernel(const int* __restrict__ csr, const int* __restrict__ offs,
                                 const float* __restrict__ xin,
                                 __nv_bfloat16* __restrict__ oh, __nv_bfloat16* __restrict__ ol,
                                 int N) {
    const int DIN = 4 * L;
    int g = blockIdx.x * blockDim.x + threadIdx.x;
    int node = g / L, lane = g % L;
    if (node >= N) return;
    int beg = __ldg(offs + node), end = __ldg(offs + node + 1);
    const float4* xi = (const float4*)xin;
    float4 a = make_float4(0.f, 0.f, 0.f, 0.f);
    float4 b = make_float4(0.f, 0.f, 0.f, 0.f);
    int j = beg;
    for (; j + 1 < end; j += 2) {
        int s0 = __ldg(csr + j), s1 = __ldg(csr + j + 1);
        float4 v0 = __ldg(xi + (size_t)s0 * L + lane);
        float4 v1 = __ldg(xi + (size_t)s1 * L + lane);
        a.x += v0.x; a.y += v0.y; a.z += v0.z; a.w += v0.w;
        b.x += v1.x; b.y += v1.y; b.z += v1.z; b.w += v1.w;
    }
    if (j < end) {
        int s0 = __ldg(csr + j);
        float4 v0 = __ldg(xi + (size_t)s0 * L + lane);
        a.x += v0.x; a.y += v0.y; a.z += v0.z; a.w += v0.w;
    }
    int c = end - beg;
    float inv = 1.0f / (float)(c > 0 ? c : 1);
    float4 r;
    r.x = (a.x + b.x) * inv; r.y = (a.y + b.y) * inv;
    r.z = (a.z + b.z) * inv; r.w = (a.w + b.w) * inv;

    unsigned u0 = __float_as_uint(r.x), u1 = __float_as_uint(r.y);
    unsigned u2 = __float_as_uint(r.z), u3 = __float_as_uint(r.w);
    uint2 hp;
    hp.x = __byte_perm(u0, u1, 0x7632);
    hp.y = __byte_perm(u2, u3, 0x7632);
    float l0 = r.x - __uint_as_float(u0 & 0xFFFF0000u);
    float l1 = r.y - __uint_as_float(u1 & 0xFFFF0000u);
    float l2 = r.z - __uint_as_float(u2 & 0xFFFF0000u);
    float l3 = r.w - __uint_as_float(u3 & 0xFFFF0000u);
    __nv_bfloat162 p01 = __floats2bfloat162_rn(l0, l1);
    __nv_bfloat162 p23 = __floats2bfloat162_rn(l2, l3);
    uint2 lp;
    lp.x = *reinterpret_cast<unsigned*>(&p01);
    lp.y = *reinterpret_cast<unsigned*>(&p23);
    size_t base = (size_t)node * DIN + lane * 4;
    *reinterpret_cast<uint2*>(oh + base) = hp;
    *reinterpret_cast<uint2*>(ol + base) = lp;
}

// ---------------- mma.sync bf16-split GEMM: out = relu([A0|A1] @ B^T + bias) ------
// D = Ah@Bh + Ah@Bl + Al@Bh, fp32 accum. Persistent grid 148, 256 thr = 8 warps.
// C tile 128x128; warp = 32 rows x 64 cols (2 m-frags x 8 n-tiles, m16n8k16).
// B (hi,lo) resident in SMEM stride K+8 (conflict-free frag reads: bank 4n+c);
// A streamed in 64-wide k chunks, stride 72 (bank 4r+c).
template <int K, bool EMIT>
__global__ void __launch_bounds__(256, 1)
mma_gemm(const __nv_bfloat16* __restrict__ A0h, const __nv_bfloat16* __restrict__ A0l,
         const __nv_bfloat16* __restrict__ A1h, const __nv_bfloat16* __restrict__ A1l,
         const __nv_bfloat16* __restrict__ Bh,  const __nv_bfloat16* __restrict__ Bl,
         const float* __restrict__ bias, float* __restrict__ out,
         __nv_bfloat16* __restrict__ outh, __nv_bfloat16* __restrict__ outl,
         int nrows, int ntiles) {
    constexpr int DIN  = K / 2;
    constexpr int BSTR = K + 8;
    constexpr int ASTR = 72;
    constexpr int NCH  = K / 64;
    extern __shared__ __nv_bfloat16 sm[];
    __nv_bfloat16* sBh = sm;
    __nv_bfloat16* sBl = sBh + 128 * BSTR;
    __nv_bfloat16* sAh = sBl + 128 * BSTR;
    __nv_bfloat16* sAl = sAh + 128 * ASTR;
    const int tid = threadIdx.x;
    const int w = tid >> 5, lane = tid & 31;
    const int g = lane >> 2, tg = lane & 3;
    const int mrow = (w >> 1) * 32;     // warp row base within tile
    const int ncol = (w & 1) * 64;      // warp col base within tile

    // stage B hi/lo once (persistent)
    for (int it = tid; it < 128 * (K / 8); it += 256) {
        int n = it / (K / 8), q = it % (K / 8);
        *(uint4*)&sBh[n * BSTR + q * 8] = *(const uint4*)(Bh + (size_t)n * K + q * 8);
        *(uint4*)&sBl[n * BSTR + q * 8] = *(const uint4*)(Bl + (size_t)n * K + q * 8);
    }
    __syncthreads();

    for (int tile = blockIdx.x; tile < ntiles; tile += gridDim.x) {
        const int rowBase = tile * 128;

        float acc[2][8][4];
#pragma unroll
        for (int mf = 0; mf < 2; mf++)
#pragma unroll
            for (int nt = 0; nt < 8; nt++)
#pragma unroll
                for (int q = 0; q < 4; q++) acc[mf][nt][q] = 0.f;

        for (int kc = 0; kc < NCH; kc++) {
            // stage A chunk (128 rows x 64 k, hi+lo)
            for (int it = tid; it < 1024; it += 256) {
                int row = it >> 3, q = it & 7;
                int rg = rowBase + row;
                int kg = kc * 64 + q * 8;
                uint4 vh = make_uint4(0, 0, 0, 0), vl = make_uint4(0, 0, 0, 0);
                if (rg < nrows) {
                    if (kg < DIN) {
                        vh = *(const uint4*)(A0h + (size_t)rg * DIN + kg);
                        vl = *(const uint4*)(A0l + (size_t)rg * DIN + kg);
                    } else {
                        vh = *(const uint4*)(A1h + (size_t)rg * DIN + (kg - DIN));
                        vl = *(const uint4*)(A1l + (size_t)rg * DIN + (kg - DIN));
                    }
                }
                *(uint4*)&sAh[row * ASTR + q * 8] = vh;
                *(uint4*)&sAl[row * ASTR + q * 8] = vl;
            }
            __syncthreads();

#pragma unroll
            for (int ks = 0; ks < 4; ks++) {
                const int kl = ks * 16;
                uint32_t ah[2][4], al[2][4];
#pragma unroll
                for (int mf = 0; mf < 2; mf++) {
                    int r0 = mrow + mf * 16 + g;
                    int c0 = kl + tg * 2, c1 = c0 + 8;
                    ah[mf][0] = *(const uint32_t*)&sAh[r0 * ASTR + c0];
                    ah[mf][1] = *(const uint32_t*)&sAh[(r0 + 8) * ASTR + c0];
                    ah[mf][2] = *(const uint32_t*)&sAh[r0 * ASTR + c1];
                    ah[mf][3] = *(const uint32_t*)&sAh[(r0 + 8) * ASTR + c1];
                    al[mf][0] = *(const uint32_t*)&sAl[r0 * ASTR + c0];
                    al[mf][1] = *(const uint32_t*)&sAl[(r0 + 8) * ASTR + c0];
                    al[mf][2] = *(const uint32_t*)&sAl[r0 * ASTR + c1];
                    al[mf][3] = *(const uint32_t*)&sAl[(r0 + 8) * ASTR + c1];
                }
#pragma unroll
                for (int nt = 0; nt < 8; nt++) {
                    const int n = ncol + nt * 8 + g;
                    const int kgl = kc * 64 + kl + tg * 2;
                    uint32_t bh0 = *(const uint32_t*)&sBh[n * BSTR + kgl];
                    uint32_t bh1 = *(const uint32_t*)&sBh[n * BSTR + kgl + 8];
                    uint32_t bl0 = *(const uint32_t*)&sBl[n * BSTR + kgl];
                    uint32_t bl1 = *(const uint32_t*)&sBl[n * BSTR + kgl + 8];
#pragma unroll
                    for (int mf = 0; mf < 2; mf++) {
                        MMA_BF16(acc[mf][nt], ah[mf], bh0, bh1);
                        MMA_BF16(acc[mf][nt], ah[mf], bl0, bl1);
                        MMA_BF16(acc[mf][nt], al[mf], bh0, bh1);
                    }
                }
            }
            __syncthreads();
        }

        // epilogue: c0,c1 -> row g, cols 2tg,2tg+1; c2,c3 -> row g+8
#pragma unroll
        for (int mf = 0; mf < 2; mf++) {
#pragma unroll
            for (int nt = 0; nt < 8; nt++) {
                const int col = ncol + nt * 8 + tg * 2;
                const float b0 = __ldg(bias + col), b1 = __ldg(bias + col + 1);
#pragma unroll
                for (int half = 0; half < 2; half++) {
                    const int row = rowBase + mrow + mf * 16 + g + half * 8;
                    if (row < nrows) {
                        float v0 = fmaxf(acc[mf][nt][half * 2 + 0] + b0, 0.f);
                        float v1 = fmaxf(acc[mf][nt][half * 2 + 1] + b1, 0.f);
                        *(float2*)(out + (size_t)row * 128 + col) = make_float2(v0, v1);
                        if constexpr (EMIT) {
                            unsigned u0 = __float_as_uint(v0), u1 = __float_as_uint(v1);
                            unsigned hp = __byte_perm(u0, u1, 0x7632);
                            float l0 = v0 - __uint_as_float(u0 & 0xFFFF0000u);
                            float l1 = v1 - __uint_as_float(u1 & 0xFFFF0000u);
                            __nv_bfloat162 p = __floats2bfloat162_rn(l0, l1);
                            *(unsigned*)(outh + (size_t)row * 128 + col) = hp;
                            *(unsigned*)(outl + (size_t)row * 128 + col) =
                                *reinterpret_cast<unsigned*>(&p);
                        }
                    }
                }
            }
        }
    }
}

// ---------------- launch ----------------
extern "C" void kernel_launch(void* const* d_in, const int* in_sizes, int n_in,
                              void* d_out, int out_size) {
    const float* x   = (const float*)d_in[0];
    const int*   ei  = (const int*)  d_in[1];
    const float* Wl1 = (const float*)d_in[2];
    const float* Wr1 = (const float*)d_in[3];
    const float* b1  = (const float*)d_in[4];
    const float* Wl2 = (const float*)d_in[5];
    const float* Wr2 = (const float*)d_in[6];
    const float* b2  = (const float*)d_in[7];
    float* out = (float*)d_out;

    const int E = in_sizes[1] / 2;     // 800000
    const int N = in_sizes[0] / DIN1;  // 50000

    __nv_bfloat16 *xh, *xl, *a1h, *a1l, *hh, *hl, *a2h, *a2l, *B1h, *B1l, *B2h, *B2l;
    float* h4;
    int *cnt, *offs, *cursor, *csr, *bsum;
    cudaGetSymbolAddress((void**)&xh,  g_xh);  cudaGetSymbolAddress((void**)&xl,  g_xl);
    cudaGetSymbolAddress((void**)&a1h, g_a1h); cudaGetSymbolAddress((void**)&a1l, g_a1l);
    cudaGetSymbolAddress((void**)&hh,  g_hh);  cudaGetSymbolAddress((void**)&hl,  g_hl);
    cudaGetSymbolAddress((void**)&a2h, g_a2h); cudaGetSymbolAddress((void**)&a2l, g_a2l);
    cudaGetSymbolAddress((void**)&B1h, g_B1h); cudaGetSymbolAddress((void**)&B1l, g_B1l);
    cudaGetSymbolAddress((void**)&B2h, g_B2h); cudaGetSymbolAddress((void**)&B2l, g_B2l);
    cudaGetSymbolAddress((void**)&h4,  g_h4);
    cudaGetSymbolAddress((void**)&cnt, g_cnt); cudaGetSymbolAddress((void**)&offs, g_offs);
    cudaGetSymbolAddress((void**)&cursor, g_cursor); cudaGetSymbolAddress((void**)&csr, g_csr);
    cudaGetSymbolAddress((void**)&bsum, g_bsum);

    // SMEM: (2*128*(K+8) + 2*128*72) bf16 elements
    const int SMEM1 = (2 * 128 * (128 + 8) + 2 * 128 * 72) * 2;   // 106,496 B
    const int SMEM2 = (2 * 128 * (256 + 8) + 2 * 128 * 72) * 2;   // 172,032 B
    cudaFuncSetAttribute(mma_gemm<128, true>,  cudaFuncAttributeMaxDynamicSharedMemorySize, SMEM1);
    cudaFuncSetAttribute(mma_gemm<256, false>, cudaFuncAttributeMaxDynamicSharedMemorySize, SMEM2);

    const int NB = (N + 1023) / 1024;   // 49 scan blocks (<= 64)
    const int NT = (N + 127) / 128;     // 391 row tiles
    const int PREP = NN + NN * DIN1 + 128 * 128 + 128 * 256;

    // CSR build + operand prep
    prep_kernel<<<(PREP + 255) / 256, 256>>>(x, Wl1, Wr1, Wl2, Wr2);
    count_kernel<<<(E + 255) / 256, 256>>>(ei + E, cnt, E);
    scanA_kernel<<<NB, 1024>>>(cnt, offs, bsum, N);
    scanC_kernel<<<NB, 1024>>>(offs, cursor, bsum, N, E);
    fill_kernel<<<(E + 255) / 256, 256>>>(ei, ei + E, cursor, csr, E);

    // layer 1
    aggregate_kernel<16><<<(N * 16 + 255) / 256, 256>>>(csr, offs, x, a1h, a1l, N);
    mma_gemm<128, true><<<148, 256, SMEM1>>>(a1h, a1l, xh, xl, B1h, B1l, b1,
                                             h4, hh, hl, N, NT);

    // layer 2
    aggregate_kernel<32><<<(N * 32 + 255) / 256, 256>>>(csr, offs, h4, a2h, a2l, N);
    mma_gemm<256, false><<<148, 256, SMEM2>>>(a2h, a2l, hh, hl, B2h, B2l, b2,
                                              out, nullptr, nullptr, N, NT);
}

// round 14
// speedup vs baseline: 1.8794x; 1.1045x over previous
#include <cuda_runtime.h>
#include <cuda_bf16.h>
#include <cuda_fp16.h>
#include <cstdint>

#define NN 50000
#define EMAX 800000
#define DIN1 64
#define DH 128

// ---------------- scratch (device globals; no allocation allowed) ----------------
__device__ __half g_x16[NN * DIN1];            // x as fp16 (aggregate-1 gather input)
__device__ __half g_h16[NN * DH];              // h as fp16 (aggregate-2 gather input)
__device__ float  g_agg1[NN * DIN1];           // mean-agg layer1 (fp32)
__device__ float  g_agg2[NN * DH];             // mean-agg layer2 (fp32)
__device__ float  g_h4 [NN * DH];              // h fp32 (GEMM2 self-term input)
__device__ __nv_bfloat16 g_B1h[DH * 2 * DIN1], g_B1l[DH * 2 * DIN1]; // [128,128] n-major
__device__ __nv_bfloat16 g_B2h[DH * 2 * DH],   g_B2l[DH * 2 * DH];   // [128,256] n-major
__device__ int g_cnt[NN], g_offs[NN + 1], g_cursor[NN], g_csr[EMAX];
__device__ unsigned long long g_pub[64];       // lookback-scan publications

// bf16x2 MMA via the baseline (sm_80+) path — compiles for plain sm_103 target.
#define MMA_BF16(c, a, b0, b1)                                               \
    asm volatile(                                                            \
        "mma.sync.aligned.m16n8k16.row.col.f32.bf16.bf16.f32 "               \
        "{%0,%1,%2,%3}, {%4,%5,%6,%7}, {%8,%9}, {%0,%1,%2,%3};"              \
        : "+f"((c)[0]), "+f"((c)[1]), "+f"((c)[2]), "+f"((c)[3])             \
        : "r"((a)[0]), "r"((a)[1]), "r"((a)[2]), "r"((a)[3]),                \
          "r"(b0), "r"(b1))

// ---------------- prep: zero cnt/pub + x->fp16 + build B(hi/lo) -------------------
__global__ void prep_kernel(const float* __restrict__ x,
                            const float* __restrict__ Wl1, const float* __restrict__ Wr1,
                            const float* __restrict__ Wl2, const float* __restrict__ Wr2) {
    int i = blockIdx.x * blockDim.x + threadIdx.x;
    const int n0 = NN;               // zero cnt (+ pub)
    const int n1 = NN * DIN1;        // x -> fp16
    const int n2 = 128 * 128;        // B1 split
    const int n3 = 128 * 256;        // B2 split
    if (i < n0) {
        g_cnt[i] = 0;
        if (i < 64) g_pub[i] = 0ull;
    } else if (i < n0 + n1) {
        int j = i - n0;
        g_x16[j] = __float2half_rn(x[j]);
    } else if (i < n0 + n1 + n2) {
        int j = i - n0 - n1;
        int n = j >> 7, k = j & 127;
        float v = (k < DIN1) ? Wl1[n * DIN1 + k] : Wr1[n * DIN1 + (k - DIN1)];
        unsigned u = __float_as_uint(v);
        ((unsigned short*)g_B1h)[j] = (unsigned short)(u >> 16);
        g_B1l[j] = __float2bfloat16_rn(v - __uint_as_float(u & 0xFFFF0000u));
    } else if (i < n0 + n1 + n2 + n3) {
        int j = i - n0 - n1 - n2;
        int n = j >> 8, k = j & 255;
        float v = (k < DH) ? Wl2[n * DH + k] : Wr2[n * DH + (k - DH)];
        unsigned u = __float_as_uint(v);
        ((unsigned short*)g_B2h)[j] = (unsigned short)(u >> 16);
        g_B2l[j] = __float2bfloat16_rn(v - __uint_as_float(u & 0xFFFF0000u));
    }
}

__global__ void count_kernel(const int* __restrict__ dst, int* __restrict__ cnt, int E) {
    int e = blockIdx.x * blockDim.x + threadIdx.x;
    if (e < E) atomicAdd(&cnt[__ldg(dst + e)], 1);
}

// ---- single-pass scan with decoupled lookback (all 49 blocks co-resident) -------
__global__ void scan_kernel(const int* __restrict__ cnt, int* __restrict__ offs,
                            int* __restrict__ cursor, int N, int E) {
    __shared__ int wsum[32];
    __shared__ int s_off;
    const int t = threadIdx.x, lane = t & 31, w = t >> 5;
    const int bid = blockIdx.x;
    int i = bid * 1024 + t;
    int v = (i < N) ? cnt[i] : 0;
    int x = v;
#pragma unroll
    for (int d = 1; d < 32; d <<= 1) {
        int y = __shfl_up_sync(0xffffffffu, x, d);
        if (lane >= d) x += y;
    }
    if (lane == 31) wsum[w] = x;
    if (t == 0) s_off = 0;
    __syncthreads();
    if (t < 32) {
        int y = wsum[t], z = y;
#pragma unroll
        for (int d = 1; d < 32; d <<= 1) {
            int u = __shfl_up_sync(0xffffffffu, z, d);
            if (t >= d) z += u;
        }
        wsum[t] = z - y;                 // exclusive warp offset
        if (t == 31)                     // publish block total (flag in bit 32)
            *((volatile unsigned long long*)&g_pub[bid]) =
                (1ull << 32) | (unsigned long long)(unsigned)z;
    }
    __syncthreads();
    int excl = (x - v) + wsum[w];
    // lookback: sum all predecessors' totals (spin until each is published)
    if (t < 64) {
        int total = 0;
        if (t < bid) {
            unsigned long long p;
            do { p = *((volatile unsigned long long*)&g_pub[t]); } while (!(p >> 32));
            total = (int)(unsigned)p;
        }
#pragma unroll
        for (int d = 16; d > 0; d >>= 1)
            total += __shfl_down_sync(0xffffffffu, total, d);
        if ((t & 31) == 0) atomicAdd(&s_off, total);
    }
    __syncthreads();
    if (i < N) {
        int o = excl + s_off;
        offs[i] = o;
        cursor[i] = o;
    }
    if (bid == 0 && t == 0) offs[N] = E;
}

__global__ void fill_kernel(const int* __restrict__ src, const int* __restrict__ dst,
                            int* __restrict__ cursor, int* __restrict__ csr, int E) {
    int e = blockIdx.x * blockDim.x + threadIdx.x;
    if (e < E) {
        int d = __ldg(dst + e);
        int p = atomicAdd(&cursor[d], 1);
        csr[p] = __ldg(src + e);
    }
}

// ---------------- CSR mean-aggregation (fp16 gather, fp32 accum/output) -----------
// L lanes per node; each lane owns 4 halves (8B). Row gather = L*8B contiguous.
template <int L>
__global__ void aggregate_kernel(const int* __restrict__ csr, const int* __restrict__ offs,
                                 const __half* __restrict__ xin, float* __restrict__ agg,
                                 int N) {
    const int DIN = 4 * L;
    int g = blockIdx.x * blockDim.x + threadIdx.x;
    int node = g / L, lane = g % L;
    if (node >= N) return;
    int beg = __ldg(offs + node), end = __ldg(offs + node + 1);
    const uint2* xi = (const uint2*)xin;           // 4 halves per uint2
    float4 a = make_float4(0.f, 0.f, 0.f, 0.f);
    float4 b = make_float4(0.f, 0.f, 0.f, 0.f);
    int j = beg;
    for (; j + 1 < end; j += 2) {
        int s0 = __ldg(csr + j), s1 = __ldg(csr + j + 1);
        uint2 v0 = __ldg(xi + (size_t)s0 * L + lane);
        uint2 v1 = __ldg(xi + (size_t)s1 * L + lane);
        float2 p0 = __half22float2(*(__half2*)&v0.x), p1 = __half22float2(*(__half2*)&v0.y);
        float2 q0 = __half22float2(*(__half2*)&v1.x), q1 = __half22float2(*(__half2*)&v1.y);
        a.x += p0.x; a.y += p0.y; a.z += p1.x; a.w += p1.y;
        b.x += q0.x; b.y += q0.y; b.z += q1.x; b.w += q1.y;
    }
    if (j < end) {
        int s0 = __ldg(csr + j);
        uint2 v0 = __ldg(xi + (size_t)s0 * L + lane);
        float2 p0 = __half22float2(*(__half2*)&v0.x), p1 = __half22float2(*(__half2*)&v0.y);
        a.x += p0.x; a.y += p0.y; a.z += p1.x; a.w += p1.y;
    }
    int c = end - beg;
    float inv = 1.0f / (float)(c > 0 ? c : 1);
    float4 r;
    r.x = (a.x + b.x) * inv; r.y = (a.y + b.y) * inv;
    r.z = (a.z + b.z) * inv; r.w = (a.w + b.w) * inv;
    ((float4*)agg)[(size_t)node * L + lane] = r;
}

// ---------------- mma.sync bf16-split GEMM: out = relu([A0|A1] @ B^T + bias) ------
// A0/A1 are fp32; hi/lo bf16 split happens INLINE during SMEM staging (exact
// fp32-truncate hi + rn lo). D = Ah@Bh + Ah@Bl + Al@Bh, fp32 accum.
// Persistent grid 148, 256 thr = 8 warps; C tile 128x128; warp = 32r x 64c.
template <int K, bool EMIT>
__global__ void __launch_bounds__(256, 1)
mma_gemm(const float* __restrict__ A0, const float* __restrict__ A1,
         const __nv_bfloat16* __restrict__ Bh, const __nv_bfloat16* __restrict__ Bl,
         const float* __restrict__ bias, float* __restrict__ out,
         __half* __restrict__ out16, int nrows, int ntiles) {
    constexpr int DIN  = K / 2;
    constexpr int BSTR = K + 8;
    constexpr int ASTR = 72;
    constexpr int NCH  = K / 64;
    extern __shared__ __nv_bfloat16 sm[];
    __nv_bfloat16* sBh = sm;
    __nv_bfloat16* sBl = sBh + 128 * BSTR;
    __nv_bfloat16* sAh = sBl + 128 * BSTR;
    __nv_bfloat16* sAl = sAh + 128 * ASTR;
    const int tid = threadIdx.x;
    const int w = tid >> 5, lane = tid & 31;
    const int g = lane >> 2, tg = lane & 3;
    const int mrow = (w >> 1) * 32;
    const int ncol = (w & 1) * 64;

    // stage B hi/lo once (persistent)
    for (int it = tid; it < 128 * (K / 8); it += 256) {
        int n = it / (K / 8), q = it % (K / 8);
        *(uint4*)&sBh[n * BSTR + q * 8] = *(const uint4*)(Bh + (size_t)n * K + q * 8);
        *(uint4*)&sBl[n * BSTR + q * 8] = *(const uint4*)(Bl + (size_t)n * K + q * 8);
    }
    __syncthreads();

    for (int tile = blockIdx.x; tile < ntiles; tile += gridDim.x) {
        const int rowBase = tile * 128;

        float acc[2][8][4];
#pragma unroll
        for (int mf = 0; mf < 2; mf++)
#pragma unroll
            for (int nt = 0; nt < 8; nt++)
#pragma unroll
                for (int q = 0; q < 4; q++) acc[mf][nt][q] = 0.f;

        for (int kc = 0; kc < NCH; kc++) {
            // stage A chunk (128 rows x 64 k) with inline fp32 -> bf16 hi/lo split
            for (int it = tid; it < 1024; it += 256) {
                int row = it >> 3, q = it & 7;
                int rg = rowBase + row;
                int kg = kc * 64 + q * 8;
                uint4 vh = make_uint4(0, 0, 0, 0), vl = make_uint4(0, 0, 0, 0);
                if (rg < nrows) {
                    const float* s = (kg < DIN) ? (A0 + (size_t)rg * DIN + kg)
                                                : (A1 + (size_t)rg * DIN + (kg - DIN));
                    float4 f0 = __ldg((const float4*)s);
                    float4 f1 = __ldg((const float4*)(s + 4));
                    unsigned u0 = __float_as_uint(f0.x), u1 = __float_as_uint(f0.y);
                    unsigned u2 = __float_as_uint(f0.z), u3 = __float_as_uint(f0.w);
                    unsigned u4 = __float_as_uint(f1.x), u5 = __float_as_uint(f1.y);
                    unsigned u6 = __float_as_uint(f1.z), u7 = __float_as_uint(f1.w);
                    vh.x = __byte_perm(u0, u1, 0x7632); vh.y = __byte_perm(u2, u3, 0x7632);
                    vh.z = __byte_perm(u4, u5, 0x7632); vh.w = __byte_perm(u6, u7, 0x7632);
                    __nv_bfloat162 l0 = __floats2bfloat162_rn(
                        f0.x - __uint_as_float(u0 & 0xFFFF0000u),
                        f0.y - __uint_as_float(u1 & 0xFFFF0000u));
                    __nv_bfloat162 l1 = __floats2bfloat162_rn(
                        f0.z - __uint_as_float(u2 & 0xFFFF0000u),
                        f0.w - __uint_as_float(u3 & 0xFFFF0000u));
                    __nv_bfloat162 l2 = __floats2bfloat162_rn(
                        f1.x - __uint_as_float(u4 & 0xFFFF0000u),
                        f1.y - __uint_as_float(u5 & 0xFFFF0000u));
                    __nv_bfloat162 l3 = __floats2bfloat162_rn(
                        f1.z - __uint_as_float(u6 & 0xFFFF0000u),
                        f1.w - __uint_as_float(u7 & 0xFFFF0000u));
                    vl.x = *reinterpret_cast<unsigned*>(&l0);
                    vl.y = *reinterpret_cast<unsigned*>(&l1);
                    vl.z = *reinterpret_cast<unsigned*>(&l2);
                    vl.w = *reinterpret_cast<unsigned*>(&l3);
                }
                *(uint4*)&sAh[row * ASTR + q * 8] = vh;
                *(uint4*)&sAl[row * ASTR + q * 8] = vl;
            }
            __syncthreads();

#pragma unroll
            for (int ks = 0; ks < 4; ks++) {
                const int kl = ks * 16;
                uint32_t ah[2][4], al[2][4];
#pragma unroll
                for (int mf = 0; mf < 2; mf++) {
                    int r0 = mrow + mf * 16 + g;
                    int c0 = kl + tg * 2, c1 = c0 + 8;
                    ah[mf][0] = *(const uint32_t*)&sAh[r0 * ASTR + c0];
                    ah[mf][1] = *(const uint32_t*)&sAh[(r0 + 8) * ASTR + c0];
                    ah[mf][2] = *(const uint32_t*)&sAh[r0 * ASTR + c1];
                    ah[mf][3] = *(const uint32_t*)&sAh[(r0 + 8) * ASTR + c1];
                    al[mf][0] = *(const uint32_t*)&sAl[r0 * ASTR + c0];
                    al[mf][1] = *(const uint32_t*)&sAl[(r0 + 8) * ASTR + c0];
                    al[mf][2] = *(const uint32_t*)&sAl[r0 * ASTR + c1];
                    al[mf][3] = *(const uint32_t*)&sAl[(r0 + 8) * ASTR + c1];
                }
#pragma unroll
                for (int nt = 0; nt < 8; nt++) {
                    const int n = ncol + nt * 8 + g;
                    const int kgl = kc * 64 + kl + tg * 2;
                    uint32_t bh0 = *(const uint32_t*)&sBh[n * BSTR + kgl];
                    uint32_t bh1 = *(const uint32_t*)&sBh[n * BSTR + kgl + 8];
                    uint32_t bl0 = *(const uint32_t*)&sBl[n * BSTR + kgl];
                    uint32_t bl1 = *(const uint32_t*)&sBl[n * BSTR + kgl + 8];
#pragma unroll
                    for (int mf = 0; mf < 2; mf++) {
                        MMA_BF16(acc[mf][nt], ah[mf], bh0, bh1);
                        MMA_BF16(acc[mf][nt], ah[mf], bl0, bl1);
                        MMA_BF16(acc[mf][nt], al[mf], bh0, bh1);
                    }
                }
            }
            __syncthreads();
        }

        // epilogue: c0,c1 -> row g, cols 2tg,2tg+1; c2,c3 -> row g+8
#pragma unroll
        for (int mf = 0; mf < 2; mf++) {
#pragma unroll
            for (int nt = 0; nt < 8; nt++) {
                const int col = ncol + nt * 8 + tg * 2;
                const float b0 = __ldg(bias + col), b1 = __ldg(bias + col + 1);
#pragma unroll
                for (int half = 0; half < 2; half++) {
                    const int row = rowBase + mrow + mf * 16 + g + half * 8;
                    if (row < nrows) {
                        float v0 = fmaxf(acc[mf][nt][half * 2 + 0] + b0, 0.f);
                        float v1 = fmaxf(acc[mf][nt][half * 2 + 1] + b1, 0.f);
                        *(float2*)(out + (size_t)row * 128 + col) = make_float2(v0, v1);
                        if constexpr (EMIT) {
                            __half2 p = __floats2half2_rn(v0, v1);
                            *(__half2*)(out16 + (size_t)row * 128 + col) = p;
                        }
                    }
                }
            }
        }
    }
}

// ---------------- launch ----------------
extern "C" void kernel_launch(void* const* d_in, const int* in_sizes, int n_in,
                              void* d_out, int out_size) {
    const float* x   = (const float*)d_in[0];
    const int*   ei  = (const int*)  d_in[1];
    const float* Wl1 = (const float*)d_in[2];
    const float* Wr1 = (const float*)d_in[3];
    const float* b1  = (const float*)d_in[4];
    const float* Wl2 = (const float*)d_in[5];
    const float* Wr2 = (const float*)d_in[6];
    const float* b2  = (const float*)d_in[7];
    float* out = (float*)d_out;

    const int E = in_sizes[1] / 2;     // 800000
    const int N = in_sizes[0] / DIN1;  // 50000

    __half *x16, *h16;
    float *agg1, *agg2, *h4;
    __nv_bfloat16 *B1h, *B1l, *B2h, *B2l;
    int *cnt, *offs, *cursor, *csr;
    cudaGetSymbolAddress((void**)&x16,  g_x16);  cudaGetSymbolAddress((void**)&h16, g_h16);
    cudaGetSymbolAddress((void**)&agg1, g_agg1); cudaGetSymbolAddress((void**)&agg2, g_agg2);
    cudaGetSymbolAddress((void**)&h4,   g_h4);
    cudaGetSymbolAddress((void**)&B1h,  g_B1h);  cudaGetSymbolAddress((void**)&B1l, g_B1l);
    cudaGetSymbolAddress((void**)&B2h,  g_B2h);  cudaGetSymbolAddress((void**)&B2l, g_B2l);
    cudaGetSymbolAddress((void**)&cnt,  g_cnt);  cudaGetSymbolAddress((void**)&offs, g_offs);
    cudaGetSymbolAddress((void**)&cursor, g_cursor); cudaGetSymbolAddress((void**)&csr, g_csr);

    const int SMEM1 = (2 * 128 * (128 + 8) + 2 * 128 * 72) * 2;   // 106,496 B
    const int SMEM2 = (2 * 128 * (256 + 8) + 2 * 128 * 72) * 2;   // 172,032 B
    cudaFuncSetAttribute(mma_gemm<128, true>,  cudaFuncAttributeMaxDynamicSharedMemorySize, SMEM1);
    cudaFuncSetAttribute(mma_gemm<256, false>, cudaFuncAttributeMaxDynamicSharedMemorySize, SMEM2);

    const int NB = (N + 1023) / 1024;   // 49 scan blocks (<= 64; all co-resident)
    const int NT = (N + 127) / 128;     // 391 row tiles
    const int PREP = NN + NN * DIN1 + 128 * 128 + 128 * 256;

    // CSR build + operand prep
    prep_kernel<<<(PREP + 255) / 256, 256>>>(x, Wl1, Wr1, Wl2, Wr2);
    count_kernel<<<(E + 255) / 256, 256>>>(ei + E, cnt, E);
    scan_kernel<<<NB, 1024>>>(cnt, offs, cursor, N, E);
    fill_kernel<<<(E + 255) / 256, 256>>>(ei, ei + E, cursor, csr, E);

    // layer 1: aggregate fp16 gather -> fp32; GEMM splits inline
    aggregate_kernel<16><<<(N * 16 + 255) / 256, 256>>>(csr, offs, x16, agg1, N);
    mma_gemm<128, true><<<148, 256, SMEM1>>>(agg1, x, B1h, B1l, b1, h4, h16, N, NT);

    // layer 2
    aggregate_kernel<32><<<(N * 32 + 255) / 256, 256>>>(csr, offs, h16, agg2, N);
    mma_gemm<256, false><<<148, 256, SMEM2>>>(agg2, h4, B2h, B2l, b2, out, nullptr, N, NT);
}

// round 15
// speedup vs baseline: 1.9216x; 1.0224x over previous
#include <cuda_runtime.h>
#include <cuda_bf16.h>
#include <cuda_fp16.h>
#include <cstdint>

#define NN 50000
#define EMAX 800000
#define DIN1 64
#define DH 128

// ---------------- scratch (device globals; no allocation allowed) ----------------
__device__ __half g_x16[NN * DIN1];            // x as fp16 (aggregate-1 gather input)
__device__ __half g_h16[NN * DH];              // h as fp16 (aggregate-2 gather input)
__device__ float  g_agg1[NN * DIN1];           // mean-agg layer1 (fp32)
__device__ float  g_agg2[NN * DH];             // mean-agg layer2 (fp32)
__device__ float  g_h4 [NN * DH];              // h fp32 (GEMM2 self-term input)
__device__ __nv_bfloat16 g_B1h[DH * 2 * DIN1], g_B1l[DH * 2 * DIN1]; // [128,128] n-major
__device__ __nv_bfloat16 g_B2h[DH * 2 * DH],   g_B2l[DH * 2 * DH];   // [128,256] n-major
__device__ int g_cnt[NN], g_offs[NN + 1], g_cursor[NN], g_csr[EMAX];
__device__ unsigned long long g_pub[64];       // lookback-scan publications

// bf16x2 MMA via the baseline (sm_80+) path — compiles for plain sm_103 target.
#define MMA_BF16(c, a, b0, b1)                                               \
    asm volatile(                                                            \
        "mma.sync.aligned.m16n8k16.row.col.f32.bf16.bf16.f32 "               \
        "{%0,%1,%2,%3}, {%4,%5,%6,%7}, {%8,%9}, {%0,%1,%2,%3};"              \
        : "+f"((c)[0]), "+f"((c)[1]), "+f"((c)[2]), "+f"((c)[3])             \
        : "r"((a)[0]), "r"((a)[1]), "r"((a)[2]), "r"((a)[3]),                \
          "r"(b0), "r"(b1))

// ---------------- prep: zero cnt/pub + x->fp16 + build B(hi/lo) -------------------
__global__ void prep_kernel(const float* __restrict__ x,
                            const float* __restrict__ Wl1, const float* __restrict__ Wr1,
                            const float* __restrict__ Wl2, const float* __restrict__ Wr2) {
    int i = blockIdx.x * blockDim.x + threadIdx.x;
    const int n0 = NN;               // zero cnt (+ pub)
    const int n1 = NN * DIN1;        // x -> fp16
    const int n2 = 128 * 128;        // B1 split
    const int n3 = 128 * 256;        // B2 split
    if (i < n0) {
        g_cnt[i] = 0;
        if (i < 64) g_pub[i] = 0ull;
    } else if (i < n0 + n1) {
        int j = i - n0;
        g_x16[j] = __float2half_rn(x[j]);
    } else if (i < n0 + n1 + n2) {
        int j = i - n0 - n1;
        int n = j >> 7, k = j & 127;
        float v = (k < DIN1) ? Wl1[n * DIN1 + k] : Wr1[n * DIN1 + (k - DIN1)];
        unsigned u = __float_as_uint(v);
        ((unsigned short*)g_B1h)[j] = (unsigned short)(u >> 16);
        g_B1l[j] = __float2bfloat16_rn(v - __uint_as_float(u & 0xFFFF0000u));
    } else if (i < n0 + n1 + n2 + n3) {
        int j = i - n0 - n1 - n2;
        int n = j >> 8, k = j & 255;
        float v = (k < DH) ? Wl2[n * DH + k] : Wr2[n * DH + (k - DH)];
        unsigned u = __float_as_uint(v);
        ((unsigned short*)g_B2h)[j] = (unsigned short)(u >> 16);
        g_B2l[j] = __float2bfloat16_rn(v - __uint_as_float(u & 0xFFFF0000u));
    }
}

// ---- count: 4 edges/thread (int4 load, no-return atomics -> REDG, MLP=4) --------
__global__ void count_kernel(const int* __restrict__ dst, int* __restrict__ cnt, int E) {
    int e4 = (blockIdx.x * blockDim.x + threadIdx.x) * 4;
    if (e4 + 3 < E) {
        int4 d = __ldg((const int4*)(dst + e4));
        atomicAdd(&cnt[d.x], 1);
        atomicAdd(&cnt[d.y], 1);
        atomicAdd(&cnt[d.z], 1);
        atomicAdd(&cnt[d.w], 1);
    } else {
        for (int e = e4; e < E; e++) atomicAdd(&cnt[__ldg(dst + e)], 1);
    }
}

// ---- single-pass scan with decoupled lookback (all 49 blocks co-resident) -------
__global__ void scan_kernel(const int* __restrict__ cnt, int* __restrict__ offs,
                            int* __restrict__ cursor, int N, int E) {
    __shared__ int wsum[32];
    __shared__ int s_off;
    const int t = threadIdx.x, lane = t & 31, w = t >> 5;
    const int bid = blockIdx.x;
    int i = bid * 1024 + t;
    int v = (i < N) ? cnt[i] : 0;
    int x = v;
#pragma unroll
    for (int d = 1; d < 32; d <<= 1) {
        int y = __shfl_up_sync(0xffffffffu, x, d);
        if (lane >= d) x += y;
    }
    if (lane == 31) wsum[w] = x;
    if (t == 0) s_off = 0;
    __syncthreads();
    if (t < 32) {
        int y = wsum[t], z = y;
#pragma unroll
        for (int d = 1; d < 32; d <<= 1) {
            int u = __shfl_up_sync(0xffffffffu, z, d);
            if (t >= d) z += u;
        }
        wsum[t] = z - y;                 // exclusive warp offset
        if (t == 31)                     // publish block total (flag in bit 32)
            *((volatile unsigned long long*)&g_pub[bid]) =
                (1ull << 32) | (unsigned long long)(unsigned)z;
    }
    __syncthreads();
    int excl = (x - v) + wsum[w];
    // lookback: sum all predecessors' totals (spin until each is published)
    if (t < 64) {
        int total = 0;
        if (t < bid) {
            unsigned long long p;
            do { p = *((volatile unsigned long long*)&g_pub[t]); } while (!(p >> 32));
            total = (int)(unsigned)p;
        }
#pragma unroll
        for (int d = 16; d > 0; d >>= 1)
            total += __shfl_down_sync(0xffffffffu, total, d);
        if ((t & 31) == 0) atomicAdd(&s_off, total);
    }
    __syncthreads();
    if (i < N) {
        int o = excl + s_off;
        offs[i] = o;
        cursor[i] = o;
    }
    if (bid == 0 && t == 0) offs[N] = E;
}

// ---- fill: 4 edges/thread (int4 loads, 4 independent atomic+store chains) -------
__global__ void fill_kernel(const int* __restrict__ src, const int* __restrict__ dst,
                            int* __restrict__ cursor, int* __restrict__ csr, int E) {
    int e4 = (blockIdx.x * blockDim.x + threadIdx.x) * 4;
    if (e4 + 3 < E) {
        int4 s = __ldg((const int4*)(src + e4));
        int4 d = __ldg((const int4*)(dst + e4));
        int p0 = atomicAdd(&cursor[d.x], 1);
        int p1 = atomicAdd(&cursor[d.y], 1);
        int p2 = atomicAdd(&cursor[d.z], 1);
        int p3 = atomicAdd(&cursor[d.w], 1);
        csr[p0] = s.x;
        csr[p1] = s.y;
        csr[p2] = s.z;
        csr[p3] = s.w;
    } else {
        for (int e = e4; e < E; e++) {
            int dd = __ldg(dst + e);
            int p = atomicAdd(&cursor[dd], 1);
            csr[p] = __ldg(src + e);
        }
    }
}

// ---------------- CSR mean-aggregation (fp16 gather, fp32 accum/output) -----------
// L lanes per node; each lane owns 4 halves (8B). Row gather = L*8B contiguous.
template <int L>
__global__ void aggregate_kernel(const int* __restrict__ csr, const int* __restrict__ offs,
                                 const __half* __restrict__ xin, float* __restrict__ agg,
                                 int N) {
    const int DIN = 4 * L;
    int g = blockIdx.x * blockDim.x + threadIdx.x;
    int node = g / L, lane = g % L;
    if (node >= N) return;
    int beg = __ldg(offs + node), end = __ldg(offs + node + 1);
    const uint2* xi = (const uint2*)xin;           // 4 halves per uint2
    float4 a = make_float4(0.f, 0.f, 0.f, 0.f);
    float4 b = make_float4(0.f, 0.f, 0.f, 0.f);
    int j = beg;
    for (; j + 1 < end; j += 2) {
        int s0 = __ldg(csr + j), s1 = __ldg(csr + j + 1);
        uint2 v0 = __ldg(xi + (size_t)s0 * L + lane);
        uint2 v1 = __ldg(xi + (size_t)s1 * L + lane);
        float2 p0 = __half22float2(*(__half2*)&v0.x), p1 = __half22float2(*(__half2*)&v0.y);
        float2 q0 = __half22float2(*(__half2*)&v1.x), q1 = __half22float2(*(__half2*)&v1.y);
        a.x += p0.x; a.y += p0.y; a.z += p1.x; a.w += p1.y;
        b.x += q0.x; b.y += q0.y; b.z += q1.x; b.w += q1.y;
    }
    if (j < end) {
        int s0 = __ldg(csr + j);
        uint2 v0 = __ldg(xi + (size_t)s0 * L + lane);
        float2 p0 = __half22float2(*(__half2*)&v0.x), p1 = __half22float2(*(__half2*)&v0.y);
        a.x += p0.x; a.y += p0.y; a.z += p1.x; a.w += p1.y;
    }
    int c = end - beg;
    float inv = 1.0f / (float)(c > 0 ? c : 1);
    float4 r;
    r.x = (a.x + b.x) * inv; r.y = (a.y + b.y) * inv;
    r.z = (a.z + b.z) * inv; r.w = (a.w + b.w) * inv;
    ((float4*)agg)[(size_t)node * L + lane] = r;
}

// ---------------- mma.sync bf16-split GEMM: out = relu([A0|A1] @ B^T + bias) ------
// A0/A1 are fp32; hi/lo bf16 split happens INLINE during SMEM staging (exact
// fp32-truncate hi + rn lo). D = Ah@Bh + Ah@Bl + Al@Bh, fp32 accum.
// Persistent grid 148, 256 thr = 8 warps; C tile 128x128; warp = 32r x 64c.
template <int K, bool EMIT>
__global__ void __launch_bounds__(256, 1)
mma_gemm(const float* __restrict__ A0, const float* __restrict__ A1,
         const __nv_bfloat16* __restrict__ Bh, const __nv_bfloat16* __restrict__ Bl,
         const float* __restrict__ bias, float* __restrict__ out,
         __half* __restrict__ out16, int nrows, int ntiles) {
    constexpr int DIN  = K / 2;
    constexpr int BSTR = K + 8;
    constexpr int ASTR = 72;
    constexpr int NCH  = K / 64;
    extern __shared__ __nv_bfloat16 sm[];
    __nv_bfloat16* sBh = sm;
    __nv_bfloat16* sBl = sBh + 128 * BSTR;
    __nv_bfloat16* sAh = sBl + 128 * BSTR;
    __nv_bfloat16* sAl = sAh + 128 * ASTR;
    const int tid = threadIdx.x;
    const int w = tid >> 5, lane = tid & 31;
    const int g = lane >> 2, tg = lane & 3;
    const int mrow = (w >> 1) * 32;
    const int ncol = (w & 1) * 64;

    // stage B hi/lo once (persistent)
    for (int it = tid; it < 128 * (K / 8); it += 256) {
        int n = it / (K / 8), q = it % (K / 8);
        *(uint4*)&sBh[n * BSTR + q * 8] = *(const uint4*)(Bh + (size_t)n * K + q * 8);
        *(uint4*)&sBl[n * BSTR + q * 8] = *(const uint4*)(Bl + (size_t)n * K + q * 8);
    }
    __syncthreads();

    for (int tile = blockIdx.x; tile < ntiles; tile += gridDim.x) {
        const int rowBase = tile * 128;

        float acc[2][8][4];
#pragma unroll
        for (int mf = 0; mf < 2; mf++)
#pragma unroll
            for (int nt = 0; nt < 8; nt++)
#pragma unroll
                for (int q = 0; q < 4; q++) acc[mf][nt][q] = 0.f;

        for (int kc = 0; kc < NCH; kc++) {
            // stage A chunk (128 rows x 64 k) with inline fp32 -> bf16 hi/lo split
            for (int it = tid; it < 1024; it += 256) {
                int row = it >> 3, q = it & 7;
                int rg = rowBase + row;
                int kg = kc * 64 + q * 8;
                uint4 vh = make_uint4(0, 0, 0, 0), vl = make_uint4(0, 0, 0, 0);
                if (rg < nrows) {
                    const float* s = (kg < DIN) ? (A0 + (size_t)rg * DIN + kg)
                                                : (A1 + (size_t)rg * DIN + (kg - DIN));
                    float4 f0 = __ldg((const float4*)s);
                    float4 f1 = __ldg((const float4*)(s + 4));
                    unsigned u0 = __float_as_uint(f0.x), u1 = __float_as_uint(f0.y);
                    unsigned u2 = __float_as_uint(f0.z), u3 = __float_as_uint(f0.w);
                    unsigned u4 = __float_as_uint(f1.x), u5 = __float_as_uint(f1.y);
                    unsigned u6 = __float_as_uint(f1.z), u7 = __float_as_uint(f1.w);
                    vh.x = __byte_perm(u0, u1, 0x7632); vh.y = __byte_perm(u2, u3, 0x7632);
                    vh.z = __byte_perm(u4, u5, 0x7632); vh.w = __byte_perm(u6, u7, 0x7632);
                    __nv_bfloat162 l0 = __floats2bfloat162_rn(
                        f0.x - __uint_as_float(u0 & 0xFFFF0000u),
                        f0.y - __uint_as_float(u1 & 0xFFFF0000u));
                    __nv_bfloat162 l1 = __floats2bfloat162_rn(
                        f0.z - __uint_as_float(u2 & 0xFFFF0000u),
                        f0.w - __uint_as_float(u3 & 0xFFFF0000u));
                    __nv_bfloat162 l2 = __floats2bfloat162_rn(
                        f1.x - __uint_as_float(u4 & 0xFFFF0000u),
                        f1.y - __uint_as_float(u5 & 0xFFFF0000u));
                    __nv_bfloat162 l3 = __floats2bfloat162_rn(
                        f1.z - __uint_as_float(u6 & 0xFFFF0000u),
                        f1.w - __uint_as_float(u7 & 0xFFFF0000u));
                    vl.x = *reinterpret_cast<unsigned*>(&l0);
                    vl.y = *reinterpret_cast<unsigned*>(&l1);
                    vl.z = *reinterpret_cast<unsigned*>(&l2);
                    vl.w = *reinterpret_cast<unsigned*>(&l3);
                }
                *(uint4*)&sAh[row * ASTR + q * 8] = vh;
                *(uint4*)&sAl[row * ASTR + q * 8] = vl;
            }
            __syncthreads();

#pragma unroll
            for (int ks = 0; ks < 4; ks++) {
                const int kl = ks * 16;
                uint32_t ah[2][4], al[2][4];
#pragma unroll
                for (int mf = 0; mf < 2; mf++) {
                    int r0 = mrow + mf * 16 + g;
                    int c0 = kl + tg * 2, c1 = c0 + 8;
                    ah[mf][0] = *(const uint32_t*)&sAh[r0 * ASTR + c0];
                    ah[mf][1] = *(const uint32_t*)&sAh[(r0 + 8) * ASTR + c0];
                    ah[mf][2] = *(const uint32_t*)&sAh[r0 * ASTR + c1];
                    ah[mf][3] = *(const uint32_t*)&sAh[(r0 + 8) * ASTR + c1];
                    al[mf][0] = *(const uint32_t*)&sAl[r0 * ASTR + c0];
                    al[mf][1] = *(const uint32_t*)&sAl[(r0 + 8) * ASTR + c0];
                    al[mf][2] = *(const uint32_t*)&sAl[r0 * ASTR + c1];
                    al[mf][3] = *(const uint32_t*)&sAl[(r0 + 8) * ASTR + c1];
                }
#pragma unroll
                for (int nt = 0; nt < 8; nt++) {
                    const int n = ncol + nt * 8 + g;
                    const int kgl = kc * 64 + kl + tg * 2;
                    uint32_t bh0 = *(const uint32_t*)&sBh[n * BSTR + kgl];
                    uint32_t bh1 = *(const uint32_t*)&sBh[n * BSTR + kgl + 8];
                    uint32_t bl0 = *(const uint32_t*)&sBl[n * BSTR + kgl];
                    uint32_t bl1 = *(const uint32_t*)&sBl[n * BSTR + kgl + 8];
#pragma unroll
                    for (int mf = 0; mf < 2; mf++) {
                        MMA_BF16(acc[mf][nt], ah[mf], bh0, bh1);
                        MMA_BF16(acc[mf][nt], ah[mf], bl0, bl1);
                        MMA_BF16(acc[mf][nt], al[mf], bh0, bh1);
                    }
                }
            }
            __syncthreads();
        }

        // epilogue: c0,c1 -> row g, cols 2tg,2tg+1; c2,c3 -> row g+8
#pragma unroll
        for (int mf = 0; mf < 2; mf++) {
#pragma unroll
            for (int nt = 0; nt < 8; nt++) {
                const int col = ncol + nt * 8 + tg * 2;
                const float b0 = __ldg(bias + col), b1 = __ldg(bias + col + 1);
#pragma unroll
                for (int half = 0; half < 2; half++) {
                    const int row = rowBase + mrow + mf * 16 + g + half * 8;
                    if (row < nrows) {
                        float v0 = fmaxf(acc[mf][nt][half * 2 + 0] + b0, 0.f);
                        float v1 = fmaxf(acc[mf][nt][half * 2 + 1] + b1, 0.f);
                        *(float2*)(out + (size_t)row * 128 + col) = make_float2(v0, v1);
                        if constexpr (EMIT) {
                            __half2 p = __floats2half2_rn(v0, v1);
                            *(__half2*)(out16 + (size_t)row * 128 + col) = p;
                        }
                    }
                }
            }
        }
    }
}

// ---------------- launch ----------------
extern "C" void kernel_launch(void* const* d_in, const int* in_sizes, int n_in,
                              void* d_out, int out_size) {
    const float* x   = (const float*)d_in[0];
    const int*   ei  = (const int*)  d_in[1];
    const float* Wl1 = (const float*)d_in[2];
    const float* Wr1 = (const float*)d_in[3];
    const float* b1  = (const float*)d_in[4];
    const float* Wl2 = (const float*)d_in[5];
    const float* Wr2 = (const float*)d_in[6];
    const float* b2  = (const float*)d_in[7];
    float* out = (float*)d_out;

    const int E = in_sizes[1] / 2;     // 800000
    const int N = in_sizes[0] / DIN1;  // 50000

    __half *x16, *h16;
    float *agg1, *agg2, *h4;
    __nv_bfloat16 *B1h, *B1l, *B2h, *B2l;
    int *cnt, *offs, *cursor, *csr;
    cudaGetSymbolAddress((void**)&x16,  g_x16);  cudaGetSymbolAddress((void**)&h16, g_h16);
    cudaGetSymbolAddress((void**)&agg1, g_agg1); cudaGetSymbolAddress((void**)&agg2, g_agg2);
    cudaGetSymbolAddress((void**)&h4,   g_h4);
    cudaGetSymbolAddress((void**)&B1h,  g_B1h);  cudaGetSymbolAddress((void**)&B1l, g_B1l);
    cudaGetSymbolAddress((void**)&B2h,  g_B2h);  cudaGetSymbolAddress((void**)&B2l, g_B2l);
    cudaGetSymbolAddress((void**)&cnt,  g_cnt);  cudaGetSymbolAddress((void**)&offs, g_offs);
    cudaGetSymbolAddress((void**)&cursor, g_cursor); cudaGetSymbolAddress((void**)&csr, g_csr);

    const int SMEM1 = (2 * 128 * (128 + 8) + 2 * 128 * 72) * 2;   // 106,496 B
    const int SMEM2 = (2 * 128 * (256 + 8) + 2 * 128 * 72) * 2;   // 172,032 B
    cudaFuncSetAttribute(mma_gemm<128, true>,  cudaFuncAttributeMaxDynamicSharedMemorySize, SMEM1);
    cudaFuncSetAttribute(mma_gemm<256, false>, cudaFuncAttributeMaxDynamicSharedMemorySize, SMEM2);

    const int NB = (N + 1023) / 1024;   // 49 scan blocks (<= 64; all co-resident)
    const int NT = (N + 127) / 128;     // 391 row tiles
    const int PREP = NN + NN * DIN1 + 128 * 128 + 128 * 256;
    const int E4 = (E + 3) / 4;         // edges processed 4-per-thread

    // CSR build + operand prep
    prep_kernel<<<(PREP + 255) / 256, 256>>>(x, Wl1, Wr1, Wl2, Wr2);
    count_kernel<<<(E4 + 255) / 256, 256>>>(ei + E, cnt, E);
    scan_kernel<<<NB, 1024>>>(cnt, offs, cursor, N, E);
    fill_kernel<<<(E4 + 255) / 256, 256>>>(ei, ei + E, cursor, csr, E);

    // layer 1: aggregate fp16 gather -> fp32; GEMM splits inline
    aggregate_kernel<16><<<(N * 16 + 255) / 256, 256>>>(csr, offs, x16, agg1, N);
    mma_gemm<128, true><<<148, 256, SMEM1>>>(agg1, x, B1h, B1l, b1, h4, h16, N, NT);

    // layer 2
    aggregate_kernel<32><<<(N * 32 + 255) / 256, 256>>>(csr, offs, h16, agg2, N);
    mma_gemm<256, false><<<148, 256, SMEM2>>>(agg2, h4, B2h, B2l, b2, out, nullptr, N, NT);
}

// round 16
// speedup vs baseline: 1.9950x; 1.0382x over previous
#include <cuda_runtime.h>
#include <cuda_bf16.h>
#include <cuda_fp16.h>
#include <cstdint>

#define NN 50000
#define EMAX 800000
#define DIN1 64
#define DH 128

// ---------------- scratch (device globals; no allocation allowed) ----------------
__device__ __half g_x16[NN * DIN1];            // x as fp16 (aggregate-1 gather input)
__device__ __half g_h16[NN * DH];              // h as fp16 (aggregate-2 gather input)
__device__ float  g_agg1[NN * DIN1];           // mean-agg layer1 (fp32)
__device__ float  g_agg2[NN * DH];             // mean-agg layer2 (fp32)
__device__ float  g_h4 [NN * DH];              // h fp32 (GEMM2 self-term input)
__device__ __nv_bfloat16 g_B1h[DH * 2 * DIN1], g_B1l[DH * 2 * DIN1]; // [128,128] n-major
__device__ __nv_bfloat16 g_B2h[DH * 2 * DH],   g_B2l[DH * 2 * DH];   // [128,256] n-major
__device__ int g_cnt[NN], g_offs[NN + 1], g_csr[EMAX], g_rank[EMAX];
__device__ unsigned long long g_pub[64];       // lookback-scan publications

// bf16x2 MMA via the baseline (sm_80+) path — compiles for plain sm_103 target.
#define MMA_BF16(c, a, b0, b1)                                               \
    asm volatile(                                                            \
        "mma.sync.aligned.m16n8k16.row.col.f32.bf16.bf16.f32 "               \
        "{%0,%1,%2,%3}, {%4,%5,%6,%7}, {%8,%9}, {%0,%1,%2,%3};"              \
        : "+f"((c)[0]), "+f"((c)[1]), "+f"((c)[2]), "+f"((c)[3])             \
        : "r"((a)[0]), "r"((a)[1]), "r"((a)[2]), "r"((a)[3]),                \
          "r"(b0), "r"(b1))

// ---------------- prep: zero cnt/pub + x->fp16 (x4 vectorized) + B(hi/lo) ---------
__global__ void prep_kernel(const float* __restrict__ x,
                            const float* __restrict__ Wl1, const float* __restrict__ Wr1,
                            const float* __restrict__ Wl2, const float* __restrict__ Wr2) {
    int i = blockIdx.x * blockDim.x + threadIdx.x;
    const int n0 = NN;                   // zero cnt (+ pub)
    const int n1 = NN * DIN1 / 4;        // x -> fp16, 4 per thread
    const int n2 = 128 * 128;            // B1 split
    const int n3 = 128 * 256;            // B2 split
    if (i < n0) {
        g_cnt[i] = 0;
        if (i < 64) g_pub[i] = 0ull;
    } else if (i < n0 + n1) {
        int j = (i - n0) * 4;
        float4 v = __ldg((const float4*)(x + j));
        __half2 p0 = __floats2half2_rn(v.x, v.y);
        __half2 p1 = __floats2half2_rn(v.z, v.w);
        uint2 o;
        o.x = *reinterpret_cast<unsigned*>(&p0);
        o.y = *reinterpret_cast<unsigned*>(&p1);
        *reinterpret_cast<uint2*>(g_x16 + j) = o;
    } else if (i < n0 + n1 + n2) {
        int j = i - n0 - n1;
        int n = j >> 7, k = j & 127;
        float v = (k < DIN1) ? Wl1[n * DIN1 + k] : Wr1[n * DIN1 + (k - DIN1)];
        unsigned u = __float_as_uint(v);
        ((unsigned short*)g_B1h)[j] = (unsigned short)(u >> 16);
        g_B1l[j] = __float2bfloat16_rn(v - __uint_as_float(u & 0xFFFF0000u));
    } else if (i < n0 + n1 + n2 + n3) {
        int j = i - n0 - n1 - n2;
        int n = j >> 8, k = j & 255;
        float v = (k < DH) ? Wl2[n * DH + k] : Wr2[n * DH + (k - DH)];
        unsigned u = __float_as_uint(v);
        ((unsigned short*)g_B2h)[j] = (unsigned short)(u >> 16);
        g_B2l[j] = __float2bfloat16_rn(v - __uint_as_float(u & 0xFFFF0000u));
    }
}

// ---- count + per-edge rank: atomic return value IS the edge's CSR slot rank -----
__global__ void count_kernel(const int* __restrict__ dst, int* __restrict__ cnt,
                             int* __restrict__ rank, int E) {
    int e2 = (blockIdx.x * blockDim.x + threadIdx.x) * 2;
    if (e2 + 1 < E) {
        int2 d = __ldg((const int2*)(dst + e2));
        int r0 = atomicAdd(&cnt[d.x], 1);
        int r1 = atomicAdd(&cnt[d.y], 1);
        *(int2*)(rank + e2) = make_int2(r0, r1);
    } else if (e2 < E) {
        int d = __ldg(dst + e2);
        rank[e2] = atomicAdd(&cnt[d], 1);
    }
}

// ---- single-pass scan with decoupled lookback (all 49 blocks co-resident) -------
__global__ void scan_kernel(const int* __restrict__ cnt, int* __restrict__ offs,
                            int N, int E) {
    __shared__ int wsum[32];
    __shared__ int s_off;
    const int t = threadIdx.x, lane = t & 31, w = t >> 5;
    const int bid = blockIdx.x;
    int i = bid * 1024 + t;
    int v = (i < N) ? cnt[i] : 0;
    int x = v;
#pragma unroll
    for (int d = 1; d < 32; d <<= 1) {
        int y = __shfl_up_sync(0xffffffffu, x, d);
        if (lane >= d) x += y;
    }
    if (lane == 31) wsum[w] = x;
    if (t == 0) s_off = 0;
    __syncthreads();
    if (t < 32) {
        int y = wsum[t], z = y;
#pragma unroll
        for (int d = 1; d < 32; d <<= 1) {
            int u = __shfl_up_sync(0xffffffffu, z, d);
            if (t >= d) z += u;
        }
        wsum[t] = z - y;                 // exclusive warp offset
        if (t == 31)                     // publish block total (flag in bit 32)
            *((volatile unsigned long long*)&g_pub[bid]) =
                (1ull << 32) | (unsigned long long)(unsigned)z;
    }
    __syncthreads();
    int excl = (x - v) + wsum[w];
    // lookback: sum all predecessors' totals (spin until each is published)
    if (t < 64) {
        int total = 0;
        if (t < bid) {
            unsigned long long p;
            do { p = *((volatile unsigned long long*)&g_pub[t]); } while (!(p >> 32));
            total = (int)(unsigned)p;
        }
#pragma unroll
        for (int d = 16; d > 0; d >>= 1)
            total += __shfl_down_sync(0xffffffffu, total, d);
        if ((t & 31) == 0) atomicAdd(&s_off, total);
    }
    __syncthreads();
    if (i < N) offs[i] = excl + s_off;
    if (bid == 0 && t == 0) offs[N] = E;
}

// ---- fill: ATOMIC-FREE — slot = offs[dst] + precomputed rank --------------------
__global__ void fill_kernel(const int* __restrict__ src, const int* __restrict__ dst,
                            const int* __restrict__ rank, const int* __restrict__ offs,
                            int* __restrict__ csr, int E) {
    int e2 = (blockIdx.x * blockDim.x + threadIdx.x) * 2;
    if (e2 + 1 < E) {
        int2 s = __ldg((const int2*)(src + e2));
        int2 d = __ldg((const int2*)(dst + e2));
        int2 r = __ldg((const int2*)(rank + e2));
        csr[__ldg(offs + d.x) + r.x] = s.x;
        csr[__ldg(offs + d.y) + r.y] = s.y;
    } else if (e2 < E) {
        csr[__ldg(offs + __ldg(dst + e2)) + __ldg(rank + e2)] = __ldg(src + e2);
    }
}

// ---------------- CSR mean-aggregation (fp16 gather, fp32 accum/output) -----------
// L lanes per node; each lane owns 4 halves (8B). Row gather = L*8B contiguous.
template <int L>
__global__ void aggregate_kernel(const int* __restrict__ csr, const int* __restrict__ offs,
                                 const __half* __restrict__ xin, float* __restrict__ agg,
                                 int N) {
    const int DIN = 4 * L;
    int g = blockIdx.x * blockDim.x + threadIdx.x;
    int node = g / L, lane = g % L;
    if (node >= N) return;
    int beg = __ldg(offs + node), end = __ldg(offs + node + 1);
    const uint2* xi = (const uint2*)xin;           // 4 halves per uint2
    float4 a = make_float4(0.f, 0.f, 0.f, 0.f);
    float4 b = make_float4(0.f, 0.f, 0.f, 0.f);
    int j = beg;
    for (; j + 1 < end; j += 2) {
        int s0 = __ldg(csr + j), s1 = __ldg(csr + j + 1);
        uint2 v0 = __ldg(xi + (size_t)s0 * L + lane);
        uint2 v1 = __ldg(xi + (size_t)s1 * L + lane);
        float2 p0 = __half22float2(*(__half2*)&v0.x), p1 = __half22float2(*(__half2*)&v0.y);
        float2 q0 = __half22float2(*(__half2*)&v1.x), q1 = __half22float2(*(__half2*)&v1.y);
        a.x += p0.x; a.y += p0.y; a.z += p1.x; a.w += p1.y;
        b.x += q0.x; b.y += q0.y; b.z += q1.x; b.w += q1.y;
    }
    if (j < end) {
        int s0 = __ldg(csr + j);
        uint2 v0 = __ldg(xi + (size_t)s0 * L + lane);
        float2 p0 = __half22float2(*(__half2*)&v0.x), p1 = __half22float2(*(__half2*)&v0.y);
        a.x += p0.x; a.y += p0.y; a.z += p1.x; a.w += p1.y;
    }
    int c = end - beg;
    float inv = 1.0f / (float)(c > 0 ? c : 1);
    float4 r;
    r.x = (a.x + b.x) * inv; r.y = (a.y + b.y) * inv;
    r.z = (a.z + b.z) * inv; r.w = (a.w + b.w) * inv;
    ((float4*)agg)[(size_t)node * L + lane] = r;
}

// ---------------- mma.sync bf16-split GEMM: out = relu([A0|A1] @ B^T + bias) ------
// A0/A1 are fp32; hi/lo bf16 split happens INLINE during SMEM staging (exact
// fp32-truncate hi + rn lo). D = Ah@Bh + Ah@Bl + Al@Bh, fp32 accum.
// Persistent grid 148, 256 thr = 8 warps; C tile 128x128; warp = 32r x 64c.
template <int K, bool EMIT>
__global__ void __launch_bounds__(256, 1)
mma_gemm(const float* __restrict__ A0, const float* __restrict__ A1,
         const __nv_bfloat16* __restrict__ Bh, const __nv_bfloat16* __restrict__ Bl,
         const float* __restrict__ bias, float* __restrict__ out,
         __half* __restrict__ out16, int nrows, int ntiles) {
    constexpr int DIN  = K / 2;
    constexpr int BSTR = K + 8;
    constexpr int ASTR = 72;
    constexpr int NCH  = K / 64;
    extern __shared__ __nv_bfloat16 sm[];
    __nv_bfloat16* sBh = sm;
    __nv_bfloat16* sBl = sBh + 128 * BSTR;
    __nv_bfloat16* sAh = sBl + 128 * BSTR;
    __nv_bfloat16* sAl = sAh + 128 * ASTR;
    const int tid = threadIdx.x;
    const int w = tid >> 5, lane = tid & 31;
    const int g = lane >> 2, tg = lane & 3;
    const int mrow = (w >> 1) * 32;
    const int ncol = (w & 1) * 64;

    // stage B hi/lo once (persistent)
    for (int it = tid; it < 128 * (K / 8); it += 256) {
        int n = it / (K / 8), q = it % (K / 8);
        *(uint4*)&sBh[n * BSTR + q * 8] = *(const uint4*)(Bh + (size_t)n * K + q * 8);
        *(uint4*)&sBl[n * BSTR + q * 8] = *(const uint4*)(Bl + (size_t)n * K + q * 8);
    }
    __syncthreads();

    for (int tile = blockIdx.x; tile < ntiles; tile += gridDim.x) {
        const int rowBase = tile * 128;

        float acc[2][8][4];
#pragma unroll
        for (int mf = 0; mf < 2; mf++)
#pragma unroll
            for (int nt = 0; nt < 8; nt++)
#pragma unroll
                for (int q = 0; q < 4; q++) acc[mf][nt][q] = 0.f;

        for (int kc = 0; kc < NCH; kc++) {
            // stage A chunk (128 rows x 64 k) with inline fp32 -> bf16 hi/lo split
            for (int it = tid; it < 1024; it += 256) {
                int row = it >> 3, q = it & 7;
                int rg = rowBase + row;
                int kg = kc * 64 + q * 8;
                uint4 vh = make_uint4(0, 0, 0, 0), vl = make_uint4(0, 0, 0, 0);
                if (rg < nrows) {
                    const float* s = (kg < DIN) ? (A0 + (size_t)rg * DIN + kg)
                                                : (A1 + (size_t)rg * DIN + (kg - DIN));
                    float4 f0 = __ldg((const float4*)s);
                    float4 f1 = __ldg((const float4*)(s + 4));
                    unsigned u0 = __float_as_uint(f0.x), u1 = __float_as_uint(f0.y);
                    unsigned u2 = __float_as_uint(f0.z), u3 = __float_as_uint(f0.w);
                    unsigned u4 = __float_as_uint(f1.x), u5 = __float_as_uint(f1.y);
                    unsigned u6 = __float_as_uint(f1.z), u7 = __float_as_uint(f1.w);
                    vh.x = __byte_perm(u0, u1, 0x7632); vh.y = __byte_perm(u2, u3, 0x7632);
                    vh.z = __byte_perm(u4, u5, 0x7632); vh.w = __byte_perm(u6, u7, 0x7632);
                    __nv_bfloat162 l0 = __floats2bfloat162_rn(
                        f0.x - __uint_as_float(u0 & 0xFFFF0000u),
                        f0.y - __uint_as_float(u1 & 0xFFFF0000u));
                    __nv_bfloat162 l1 = __floats2bfloat162_rn(
                        f0.z - __uint_as_float(u2 & 0xFFFF0000u),
                        f0.w - __uint_as_float(u3 & 0xFFFF0000u));
                    __nv_bfloat162 l2 = __floats2bfloat162_rn(
                        f1.x - __uint_as_float(u4 & 0xFFFF0000u),
                        f1.y - __uint_as_float(u5 & 0xFFFF0000u));
                    __nv_bfloat162 l3 = __floats2bfloat162_rn(
                        f1.z - __uint_as_float(u6 & 0xFFFF0000u),
                        f1.w - __uint_as_float(u7 & 0xFFFF0000u));
                    vl.x = *reinterpret_cast<unsigned*>(&l0);
                    vl.y = *reinterpret_cast<unsigned*>(&l1);
                    vl.z = *reinterpret_cast<unsigned*>(&l2);
                    vl.w = *reinterpret_cast<unsigned*>(&l3);
                }
                *(uint4*)&sAh[row * ASTR + q * 8] = vh;
                *(uint4*)&sAl[row * ASTR + q * 8] = vl;
            }
            __syncthreads();

#pragma unroll
            for (int ks = 0; ks < 4; ks++) {
                const int kl = ks * 16;
                uint32_t ah[2][4], al[2][4];
#pragma unroll
                for (int mf = 0; mf < 2; mf++) {
                    int r0 = mrow + mf * 16 + g;
                    int c0 = kl + tg * 2, c1 = c0 + 8;
                    ah[mf][0] = *(const uint32_t*)&sAh[r0 * ASTR + c0];
                    ah[mf][1] = *(const uint32_t*)&sAh[(r0 + 8) * ASTR + c0];
                    ah[mf][2] = *(const uint32_t*)&sAh[r0 * ASTR + c1];
                    ah[mf][3] = *(const uint32_t*)&sAh[(r0 + 8) * ASTR + c1];
                    al[mf][0] = *(const uint32_t*)&sAl[r0 * ASTR + c0];
                    al[mf][1] = *(const uint32_t*)&sAl[(r0 + 8) * ASTR + c0];
                    al[mf][2] = *(const uint32_t*)&sAl[r0 * ASTR + c1];
                    al[mf][3] = *(const uint32_t*)&sAl[(r0 + 8) * ASTR + c1];
                }
#pragma unroll
                for (int nt = 0; nt < 8; nt++) {
                    const int n = ncol + nt * 8 + g;
                    const int kgl = kc * 64 + kl + tg * 2;
                    uint32_t bh0 = *(const uint32_t*)&sBh[n * BSTR + kgl];
                    uint32_t bh1 = *(const uint32_t*)&sBh[n * BSTR + kgl + 8];
                    uint32_t bl0 = *(const uint32_t*)&sBl[n * BSTR + kgl];
                    uint32_t bl1 = *(const uint32_t*)&sBl[n * BSTR + kgl + 8];
#pragma unroll
                    for (int mf = 0; mf < 2; mf++) {
                        MMA_BF16(acc[mf][nt], ah[mf], bh0, bh1);
                        MMA_BF16(acc[mf][nt], ah[mf], bl0, bl1);
                        MMA_BF16(acc[mf][nt], al[mf], bh0, bh1);
                    }
                }
            }
            __syncthreads();
        }

        // epilogue: c0,c1 -> row g, cols 2tg,2tg+1; c2,c3 -> row g+8
#pragma unroll
        for (int mf = 0; mf < 2; mf++) {
#pragma unroll
            for (int nt = 0; nt < 8; nt++) {
                const int col = ncol + nt * 8 + tg * 2;
                const float b0 = __ldg(bias + col), b1 = __ldg(bias + col + 1);
#pragma unroll
                for (int half = 0; half < 2; half++) {
                    const int row = rowBase + mrow + mf * 16 + g + half * 8;
                    if (row < nrows) {
                        float v0 = fmaxf(acc[mf][nt][half * 2 + 0] + b0, 0.f);
                        float v1 = fmaxf(acc[mf][nt][half * 2 + 1] + b1, 0.f);
                        *(float2*)(out + (size_t)row * 128 + col) = make_float2(v0, v1);
                        if constexpr (EMIT) {
                            __half2 p = __floats2half2_rn(v0, v1);
                            *(__half2*)(out16 + (size_t)row * 128 + col) = p;
                        }
                    }
                }
            }
        }
    }
}

// ---------------- launch ----------------
extern "C" void kernel_launch(void* const* d_in, const int* in_sizes, int n_in,
                              void* d_out, int out_size) {
    const float* x   = (const float*)d_in[0];
    const int*   ei  = (const int*)  d_in[1];
    const float* Wl1 = (const float*)d_in[2];
    const float* Wr1 = (const float*)d_in[3];
    const float* b1  = (const float*)d_in[4];
    const float* Wl2 = (const float*)d_in[5];
    const float* Wr2 = (const float*)d_in[6];
    const float* b2  = (const float*)d_in[7];
    float* out = (float*)d_out;

    const int E = in_sizes[1] / 2;     // 800000
    const int N = in_sizes[0] / DIN1;  // 50000

    __half *x16, *h16;
    float *agg1, *agg2, *h4;
    __nv_bfloat16 *B1h, *B1l, *B2h, *B2l;
    int *cnt, *offs, *csr, *rank;
    cudaGetSymbolAddress((void**)&x16,  g_x16);  cudaGetSymbolAddress((void**)&h16, g_h16);
    cudaGetSymbolAddress((void**)&agg1, g_agg1); cudaGetSymbolAddress((void**)&agg2, g_agg2);
    cudaGetSymbolAddress((void**)&h4,   g_h4);
    cudaGetSymbolAddress((void**)&B1h,  g_B1h);  cudaGetSymbolAddress((void**)&B1l, g_B1l);
    cudaGetSymbolAddress((void**)&B2h,  g_B2h);  cudaGetSymbolAddress((void**)&B2l, g_B2l);
    cudaGetSymbolAddress((void**)&cnt,  g_cnt);  cudaGetSymbolAddress((void**)&offs, g_offs);
    cudaGetSymbolAddress((void**)&csr,  g_csr);  cudaGetSymbolAddress((void**)&rank, g_rank);

    const int SMEM1 = (2 * 128 * (128 + 8) + 2 * 128 * 72) * 2;   // 106,496 B
    const int SMEM2 = (2 * 128 * (256 + 8) + 2 * 128 * 72) * 2;   // 172,032 B
    cudaFuncSetAttribute(mma_gemm<128, true>,  cudaFuncAttributeMaxDynamicSharedMemorySize, SMEM1);
    cudaFuncSetAttribute(mma_gemm<256, false>, cudaFuncAttributeMaxDynamicSharedMemorySize, SMEM2);

    const int NB = (N + 1023) / 1024;   // 49 scan blocks (<= 64; all co-resident)
    const int NT = (N + 127) / 128;     // 391 row tiles
    const int PREP = NN + NN * DIN1 / 4 + 128 * 128 + 128 * 256;
    const int E2 = (E + 1) / 2;         // edges processed 2-per-thread

    // CSR build + operand prep
    prep_kernel<<<(PREP + 255) / 256, 256>>>(x, Wl1, Wr1, Wl2, Wr2);
    count_kernel<<<(E2 + 255) / 256, 256>>>(ei + E, cnt, rank, E);
    scan_kernel<<<NB, 1024>>>(cnt, offs, N, E);
    fill_kernel<<<(E2 + 255) / 256, 256>>>(ei, ei + E, rank, offs, csr, E);

    // layer 1: aggregate fp16 gather -> fp32; GEMM splits inline
    aggregate_kernel<16><<<(N * 16 + 255) / 256, 256>>>(csr, offs, x16, agg1, N);
    mma_gemm<128, true><<<148, 256, SMEM1>>>(agg1, x, B1h, B1l, b1, h4, h16, N, NT);

    // layer 2
    aggregate_kernel<32><<<(N * 32 + 255) / 256, 256>>>(csr, offs, h16, agg2, N);
    mma_gemm<256, false><<<148, 256, SMEM2>>>(agg2, h4, B2h, B2l, b2, out, nullptr, N, NT);
}